// round 9
// baseline (speedup 1.0000x reference)
#include <cuda_runtime.h>
#include <cuda_bf16.h>
#include <math.h>
#include <stdint.h>

#define BB 16
#define LL 1024
#define HH 1024
#define NN 64

typedef __nv_bfloat16 bf16;

// scratch (device globals — no allocation allowed)
__device__ float g_kern[HH * LL];              // kern [h][l]
__device__ bf16 g_xth[HH * BB * LL];           // x^T hi [h][b][l]
__device__ bf16 g_xtl[HH * BB * LL];           // x^T lo
__device__ bf16 g_yth[HH * BB * LL];           // y^T hi [h][b*l] (k-major for GEMM)
__device__ bf16 g_ytl[HH * BB * LL];           // y^T lo
__device__ bf16 g_whT[2048 * 1024];            // W^T hi [n][k]
__device__ bf16 g_wlT[2048 * 1024];            // W^T lo [n][k]

// ---- helpers ----------------------------------------------------------------
__device__ __forceinline__ uint32_t smem_u32(const void* p) {
    uint32_t a;
    asm("{ .reg .u64 t; cvta.to.shared.u64 t, %1; cvt.u32.u64 %0, t; }"
        : "=r"(a) : "l"(p));
    return a;
}
#define CP_ASYNC16(dst, src) \
    asm volatile("cp.async.cg.shared.global [%0], [%1], 16;" :: "r"(dst), "l"(src))
#define CP_COMMIT() asm volatile("cp.async.commit_group;" ::: "memory")
#define CP_WAIT2() asm volatile("cp.async.wait_group 2;" ::: "memory")
#define CP_WAIT1() asm volatile("cp.async.wait_group 1;" ::: "memory")
#define CP_WAIT0() asm volatile("cp.async.wait_group 0;" ::: "memory")

__device__ __forceinline__ void ldsm_x4(uint32_t* r, uint32_t addr) {
    asm volatile("ldmatrix.sync.aligned.m8n8.x4.shared.b16 {%0,%1,%2,%3}, [%4];"
                 : "=r"(r[0]), "=r"(r[1]), "=r"(r[2]), "=r"(r[3]) : "r"(addr));
}
__device__ __forceinline__ void ldsm_x4t(uint32_t* r, uint32_t addr) {
    asm volatile("ldmatrix.sync.aligned.m8n8.x4.trans.shared.b16 {%0,%1,%2,%3}, [%4];"
                 : "=r"(r[0]), "=r"(r[1]), "=r"(r[2]), "=r"(r[3]) : "r"(addr));
}
__device__ __forceinline__ void mma_bf16(float* c, const uint32_t* a,
                                         const uint32_t* b) {
    asm volatile(
        "mma.sync.aligned.m16n8k16.row.col.f32.bf16.bf16.f32 "
        "{%0,%1,%2,%3}, {%4,%5,%6,%7}, {%8,%9}, {%0,%1,%2,%3};"
        : "+f"(c[0]), "+f"(c[1]), "+f"(c[2]), "+f"(c[3])
        : "r"(a[0]), "r"(a[1]), "r"(a[2]), "r"(a[3]), "r"(b[0]), "r"(b[1]));
}
__device__ __forceinline__ float gelu_tanh(float t) {
    float c = 0.7978845608028654f * (t + 0.044715f * t * t * t);
    return 0.5f * t * (1.0f + tanhf(c));
}

// ---------------------------------------------------------------------------
// Kernel 1: S4D kernel generation, L-chunked (8 chunks of 128 per h).
// ---------------------------------------------------------------------------
#define GCH 128

__global__ void k_gen(const float* __restrict__ log_dt,
                      const float* __restrict__ Arl,
                      const float* __restrict__ Aim,
                      const float* __restrict__ Cr,
                      const float* __restrict__ Ci,
                      float* __restrict__ kern) {
    int h = blockIdx.x;
    int l0 = blockIdx.y * GCH;
    int lane = threadIdx.x;
    float dt = expf(log_dt[h]);

    float zr[2], zi[2], wr[2], wi[2];
#pragma unroll
    for (int t = 0; t < 2; t++) {
        int n = lane + t * 32;
        float ar = -expf(Arl[h * NN + n]);
        float ai = Aim[h * NN + n];
        float dr = dt * ar, di = dt * ai;
        float er = expf(dr);
        float sn, cs;
        sincosf(di, &sn, &cs);
        float Er = er * cs - 1.0f, Ei = er * sn;
        float inv = 1.0f / (ar * ar + ai * ai);
        float Fr = (Er * ar + Ei * ai) * inv;
        float Fi = (Ei * ar - Er * ai) * inv;
        float cr = Cr[h * NN + n], ci = Ci[h * NN + n];
        float c0r = cr * Fr - ci * Fi;
        float c0i = cr * Fi + ci * Fr;
        float e0 = expf(dr * (float)l0);
        float s0, q0;
        sincosf(di * (float)l0, &s0, &q0);
        float pr = e0 * q0, pi = e0 * s0;
        zr[t] = c0r * pr - c0i * pi;
        zi[t] = c0r * pi + c0i * pr;
        wr[t] = er * cs;
        wi[t] = er * sn;
    }
    float* kout = kern + (size_t)h * LL + l0;
    for (int l = 0; l < GCH; l++) {
        float s = zr[0] + zr[1];
#pragma unroll
        for (int o = 16; o > 0; o >>= 1)
            s += __shfl_xor_sync(0xffffffffu, s, o);
        if (lane == 0) kout[l] = 2.0f * s;
#pragma unroll
        for (int t = 0; t < 2; t++) {
            float tr = zr[t] * wr[t] - zi[t] * wi[t];
            zi[t] = zr[t] * wi[t] + zi[t] * wr[t];
            zr[t] = tr;
        }
    }
}

// ---------------------------------------------------------------------------
// Kernel 1b: W [1024,2048] -> W^T bf16 hi/lo [2048][1024]
// ---------------------------------------------------------------------------
__global__ void k_prepW(const float* __restrict__ W,
                        bf16* __restrict__ whT, bf16* __restrict__ wlT) {
    __shared__ float t[32][33];
    int tx = threadIdx.x, ty = threadIdx.y;
    int n0 = blockIdx.x * 32, k0 = blockIdx.y * 32;
#pragma unroll
    for (int i = 0; i < 4; i++)
        t[ty + i * 8][tx] = W[(size_t)(k0 + ty + i * 8) * 2048 + n0 + tx];
    __syncthreads();
#pragma unroll
    for (int i = 0; i < 4; i++) {
        int n = n0 + ty + i * 8;
        float v = t[tx][ty + i * 8];
        bf16 h = __float2bfloat16(v);
        float lo = v - __bfloat162float(h);
        whT[(size_t)n * 1024 + k0 + tx] = h;
        wlT[(size_t)n * 1024 + k0 + tx] = __float2bfloat16(lo);
    }
}

// ---------------------------------------------------------------------------
// Kernel 1c: x [b][l][h] f32 -> x^T bf16 hi/lo [h][b][l]
// ---------------------------------------------------------------------------
__global__ void k_xt(const float* __restrict__ x,
                     bf16* __restrict__ xth, bf16* __restrict__ xtl) {
    __shared__ float t[32][33];
    int tx = threadIdx.x, ty = threadIdx.y;
    int l0 = blockIdx.x * 32, h0 = blockIdx.y * 32, b = blockIdx.z;
    const float* xb = x + (size_t)b * LL * HH;
#pragma unroll
    for (int i = 0; i < 4; i++)
        t[ty + i * 8][tx] = xb[(size_t)(l0 + ty + i * 8) * HH + h0 + tx];
    __syncthreads();
#pragma unroll
    for (int i = 0; i < 4; i++) {
        int hh = ty + i * 8;
        float v = t[tx][hh];
        bf16 hi = __float2bfloat16(v);
        float lo = v - __bfloat162float(hi);
        size_t o = (size_t)(h0 + hh) * (BB * LL) + (size_t)b * LL + l0 + tx;
        xth[o] = hi;
        xtl[o] = __float2bfloat16(lo);
    }
}

// ---------------------------------------------------------------------------
// Kernel 2: Toeplitz tensor-core causal conv + D-skip + gelu.
// SWAPPED operands vs R6: A = x (m=b=16), B = T_d (n=lout). The B(T)
// fragments are identical for both of a warp's lout tiles -> loaded once
// per kc and shared. ldsm per warp-d: 80 -> 48.
// ---------------------------------------------------------------------------
#define XP 2064
#define TP 144
#define SM_XH 0
#define SM_XL 33024
#define SM_K  66048
#define SM_T  70144
#define TBUF  18432
#define SMEM_CONV 107008

__global__ __launch_bounds__(256, 1) void k_conv_tc(
    const bf16* __restrict__ xth, const bf16* __restrict__ xtl,
    const float* __restrict__ kern, const float* __restrict__ D,
    bf16* __restrict__ yth, bf16* __restrict__ ytl) {
    extern __shared__ __align__(128) char smem[];
    uint32_t sb = smem_u32(smem);
    int tid = threadIdx.x;
    int wid = tid >> 5;
    int lane = tid & 31;
    int h = blockIdx.x;

#pragma unroll
    for (int m = 0; m < 2; m++) {
        const bf16* s0 = (m ? xtl : xth) + (size_t)h * (BB * LL);
        uint32_t d0 = sb + (m ? SM_XL : SM_XH);
        for (int i = tid; i < 2048; i += 256) {
            int b = i >> 7, g = i & 127;
            CP_ASYNC16(d0 + b * XP + g * 16, s0 + (size_t)b * LL + g * 8);
        }
    }
    CP_COMMIT();

    float* ks = (float*)(smem + SM_K);
    for (int i = tid; i < 1024; i += 256) ks[i] = kern[(size_t)h * LL + i];
    __syncthreads();

    for (int i = tid; i < 4096; i += 256) {
        int r = i >> 6, c = i & 63;
        int off = r - c;
        float v = (off >= 0) ? ks[off] : 0.0f;
        bf16 hi = __float2bfloat16(v);
        bf16 lo = __float2bfloat16(v - __bfloat162float(hi));
        *(bf16*)(smem + SM_T + r * TP + c * 2) = hi;
        *(bf16*)(smem + SM_T + 9216 + r * TP + c * 2) = lo;
    }
    CP_WAIT0();
    __syncthreads();

    // acc[t][nf][4]: C[m=b16][n=lout64] per tile, 8 n-frags of n8
    float acc[2][8][4];
#pragma unroll
    for (int t = 0; t < 2; t++)
#pragma unroll
        for (int nf = 0; nf < 8; nf++)
#pragma unroll
            for (int e = 0; e < 4; e++) acc[t][nf][e] = 0.0f;

    int li0 = wid;
    int li1 = 15 - wid;

#pragma unroll 1
    for (int d = 0; d < 16; d++) {
        int bufT = d & 1;
        if (d > 0) {
            __syncthreads();
            for (int i = tid; i < 4096; i += 256) {
                int r = i >> 6, c = i & 63;
                float v = ks[d * 64 + r - c];
                bf16 hi = __float2bfloat16(v);
                bf16 lo = __float2bfloat16(v - __bfloat162float(hi));
                *(bf16*)(smem + SM_T + bufT * TBUF + r * TP + c * 2) = hi;
                *(bf16*)(smem + SM_T + bufT * TBUF + 9216 + r * TP + c * 2) = lo;
            }
            __syncthreads();
        }
        uint32_t tH = sb + SM_T + bufT * TBUF;
        uint32_t tL = tH + 9216;
        if (li1 >= d) {
#pragma unroll
            for (int kc = 0; kc < 4; kc++) {
                // B(T) fragments: [n=lout][k=j], shared by both lout tiles
                uint32_t bh[8][2], bl[8][2];
                uint32_t boff = (((lane >> 4) & 1) * 8 + (lane & 7)) * TP +
                                kc * 32 + ((lane >> 3) & 1) * 16;
#pragma unroll
                for (int q = 0; q < 4; q++) {
                    uint32_t badr = q * 16 * TP + boff;
                    uint32_t t4[4];
                    ldsm_x4(t4, tH + badr);
                    bh[2 * q][0] = t4[0]; bh[2 * q][1] = t4[1];
                    bh[2 * q + 1][0] = t4[2]; bh[2 * q + 1][1] = t4[3];
                    ldsm_x4(t4, tL + badr);
                    bl[2 * q][0] = t4[0]; bl[2 * q][1] = t4[1];
                    bl[2 * q + 1][0] = t4[2]; bl[2 * q + 1][1] = t4[3];
                }
#pragma unroll
                for (int t = 0; t < 2; t++) {
                    int li = t ? li1 : li0;
                    if (li < d) continue;
                    int ji = li - d;
                    // A(x) fragments: [m=b16][k=j16], hi and lo
                    uint32_t a_h[4], a_l[4];
                    uint32_t arow = (lane & 15) * XP + ji * 128 + kc * 32 +
                                    (lane >> 4) * 16;
                    ldsm_x4(a_h, sb + SM_XH + arow);
                    ldsm_x4(a_l, sb + SM_XL + arow);
#pragma unroll
                    for (int nf = 0; nf < 8; nf++) {
                        mma_bf16(acc[t][nf], a_h, bh[nf]);
                        mma_bf16(acc[t][nf], a_h, bl[nf]);
                        mma_bf16(acc[t][nf], a_l, bh[nf]);
                    }
                }
            }
        }
    }

    __syncthreads();
    float Dh = D[h];
    float* epf = (float*)(smem + SM_T + wid * 4352);   // [16 b][68 f32]
#pragma unroll 1
    for (int t = 0; t < 2; t++) {
        int li = t ? li1 : li0;
        int r0 = lane >> 2, c0 = (lane & 3) * 2;
#pragma unroll
        for (int nf = 0; nf < 8; nf++) {
            int l = nf * 8 + c0;
            epf[r0 * 68 + l]           = acc[t][nf][0];
            epf[r0 * 68 + l + 1]       = acc[t][nf][1];
            epf[(r0 + 8) * 68 + l]     = acc[t][nf][2];
            epf[(r0 + 8) * 68 + l + 1] = acc[t][nf][3];
        }
        __syncwarp();
#pragma unroll
        for (int i = lane; i < 1024; i += 32) {
            int b = i >> 6, l = i & 63;
            int lout = li * 64 + l;
            float xv = __bfloat162float(*(bf16*)(smem + SM_XH + b * XP + lout * 2)) +
                       __bfloat162float(*(bf16*)(smem + SM_XL + b * XP + lout * 2));
            float v = gelu_tanh(epf[b * 68 + l] + xv * Dh);
            bf16 hi = __float2bfloat16(v);
            bf16 lo = __float2bfloat16(v - __bfloat162float(hi));
            size_t o = (size_t)h * (BB * LL) + (size_t)b * LL + lout;
            yth[o] = hi;
            ytl[o] = lo;
        }
        __syncwarp();
    }
}

// ---------------------------------------------------------------------------
// Kernel 3: mma.sync bf16x3 GEMM + bias + GLU. 3-stage cp.async pipeline.
// (unchanged from R8)
// ---------------------------------------------------------------------------
#define GAP 272
#define GABUF (32 * GAP)
#define GBP 80
#define GBBUF (256 * GBP)
#define SM_GA 0
#define SM_GB 52224
#define SMEM_GEMM 175104
#define GNS 32

__global__ __launch_bounds__(256, 1) void k_gemm_mma(
    const bf16* __restrict__ Yth, const bf16* __restrict__ Ytl,
    const bf16* __restrict__ WhT, const bf16* __restrict__ WlT,
    const float* __restrict__ bias, float* __restrict__ out) {
    extern __shared__ __align__(128) char smem[];
    uint32_t sb = smem_u32(smem);
    int tid = threadIdx.x;
    int wid = tid >> 5;
    int lane = tid & 31;
    int wm = wid >> 2;
    int wn = wid & 3;
    int N0a = blockIdx.x * 128;
    int M0 = blockIdx.y * 128;

    float acc[4][8][4];
#pragma unroll
    for (int i = 0; i < 4; i++)
#pragma unroll
        for (int j = 0; j < 8; j++)
#pragma unroll
            for (int e = 0; e < 4; e++) acc[i][j][e] = 0.0f;

#define G_ISSUE(S)                                                              \
    {                                                                           \
        int _s = (S);                                                           \
        int _buf = _s % 3;                                                      \
        int K0 = _s * 32;                                                       \
        _Pragma("unroll") for (int it = 0; it < 12; it++) {                     \
            int i = tid + it * 256;                                             \
            const bf16* src;                                                    \
            uint32_t dst;                                                       \
            if (i < 1024) {                                                     \
                int mat = i >> 9, r = (i >> 4) & 31, g = i & 15;                \
                src = (mat ? Ytl : Yth) + (size_t)(K0 + r) * 16384 + M0 + g * 8;\
                dst = sb + SM_GA + (_buf * 2 + mat) * GABUF + r * GAP + g * 16; \
            } else {                                                            \
                int j = i - 1024;                                               \
                int mat = j >> 10, r = (j >> 2) & 255, g = j & 3;               \
                int n = (r & 1) ? (1024 + N0a + (r >> 1)) : (N0a + (r >> 1));   \
                src = (mat ? WlT : WhT) + (size_t)n * 1024 + K0 + g * 8;        \
                dst = sb + SM_GB + (_buf * 2 + mat) * GBBUF + r * GBP + g * 16; \
            }                                                                   \
            CP_ASYNC16(dst, src);                                               \
        }                                                                       \
        CP_COMMIT();                                                            \
    }

    G_ISSUE(0);
    G_ISSUE(1);
#pragma unroll 1
    for (int s = 0; s < GNS; s++) {
        int buf = s % 3;
        if (s + 2 < GNS) {
            G_ISSUE(s + 2);
            CP_WAIT2();
        } else if (s + 1 < GNS) {
            CP_WAIT1();
        } else {
            CP_WAIT0();
        }
        __syncthreads();

        uint32_t aHb = sb + SM_GA + (buf * 2 + 0) * GABUF;
        uint32_t aLb = sb + SM_GA + (buf * 2 + 1) * GABUF;
        uint32_t bHb = sb + SM_GB + (buf * 2 + 0) * GBBUF;
        uint32_t bLb = sb + SM_GB + (buf * 2 + 1) * GBBUF;

#pragma unroll
        for (int kc = 0; kc < 2; kc++) {
            uint32_t a_h[4][4], a_l[4][4];
            uint32_t arow = (kc * 16 + ((lane >> 4) & 1) * 8 + (lane & 7)) * GAP;
#pragma unroll
            for (int mf = 0; mf < 4; mf++) {
                uint32_t ao = arow + (wm * 64 + mf * 16 + ((lane >> 3) & 1) * 8) * 2;
                ldsm_x4t(a_h[mf], aHb + ao);
                ldsm_x4t(a_l[mf], aLb + ao);
            }
            uint32_t boff = (((lane >> 4) & 1) * 8 + (lane & 7)) * GBP +
                            kc * 32 + ((lane >> 3) & 1) * 16;
#pragma unroll
            for (int q = 0; q < 4; q++) {
                uint32_t badr = (wn * 64 + q * 16) * GBP + boff;
                uint32_t bh[2][2], bl[2][2];
                uint32_t t4[4];
                ldsm_x4(t4, bHb + badr);
                bh[0][0] = t4[0]; bh[0][1] = t4[1];
                bh[1][0] = t4[2]; bh[1][1] = t4[3];
                ldsm_x4(t4, bLb + badr);
                bl[0][0] = t4[0]; bl[0][1] = t4[1];
                bl[1][0] = t4[2]; bl[1][1] = t4[3];
#pragma unroll
                for (int mf = 0; mf < 4; mf++)
#pragma unroll
                    for (int e = 0; e < 2; e++) {
                        int nf = 2 * q + e;
                        mma_bf16(acc[mf][nf], a_h[mf], bh[e]);
                        mma_bf16(acc[mf][nf], a_h[mf], bl[e]);
                        mma_bf16(acc[mf][nf], a_l[mf], bh[e]);
                    }
            }
        }
        __syncthreads();
    }

#pragma unroll
    for (int nf = 0; nf < 8; nf++) {
        int p = wn * 32 + nf * 4 + (lane & 3);
        int col = N0a + p;
        float ba = bias[col];
        float bg = bias[1024 + col];
#pragma unroll
        for (int mf = 0; mf < 4; mf++) {
            int m = M0 + wm * 64 + mf * 16 + (lane >> 2);
            float a0 = acc[mf][nf][0] + ba;
            float g0 = acc[mf][nf][1] + bg;
            float a1 = acc[mf][nf][2] + ba;
            float g1 = acc[mf][nf][3] + bg;
            out[(size_t)m * 1024 + col]       = a0 / (1.0f + expf(-g0));
            out[(size_t)(m + 8) * 1024 + col] = a1 / (1.0f + expf(-g1));
        }
    }
}

// ---------------------------------------------------------------------------
extern "C" void kernel_launch(void* const* d_in, const int* in_sizes, int n_in,
                              void* d_out, int out_size) {
    const float* x      = (const float*)d_in[0];
    const float* log_dt = (const float*)d_in[1];
    const float* Arl    = (const float*)d_in[2];
    const float* Aim    = (const float*)d_in[3];
    const float* Cr     = (const float*)d_in[4];
    const float* Ci     = (const float*)d_in[5];
    const float* D      = (const float*)d_in[6];
    const float* W      = (const float*)d_in[7];
    const float* bias   = (const float*)d_in[8];
    float* out = (float*)d_out;

    float* kern;
    bf16 *xth, *xtl, *yth, *ytl, *whT, *wlT;
    cudaGetSymbolAddress((void**)&kern, g_kern);
    cudaGetSymbolAddress((void**)&xth, g_xth);
    cudaGetSymbolAddress((void**)&xtl, g_xtl);
    cudaGetSymbolAddress((void**)&yth, g_yth);
    cudaGetSymbolAddress((void**)&ytl, g_ytl);
    cudaGetSymbolAddress((void**)&whT, g_whT);
    cudaGetSymbolAddress((void**)&wlT, g_wlT);

    cudaFuncSetAttribute(k_conv_tc, cudaFuncAttributeMaxDynamicSharedMemorySize,
                         SMEM_CONV);
    cudaFuncSetAttribute(k_gemm_mma, cudaFuncAttributeMaxDynamicSharedMemorySize,
                         SMEM_GEMM);

    k_gen<<<dim3(HH, LL / GCH), 32>>>(log_dt, Arl, Aim, Cr, Ci, kern);
    k_prepW<<<dim3(2048 / 32, 1024 / 32), dim3(32, 8)>>>(W, whT, wlT);
    k_xt<<<dim3(LL / 32, HH / 32, BB), dim3(32, 8)>>>(x, xth, xtl);

    k_conv_tc<<<HH, 256, SMEM_CONV>>>(xth, xtl, kern, D, yth, ytl);

    dim3 ggrid(2048 / 256, 16384 / 128);   // (8, 128)
    k_gemm_mma<<<ggrid, 256, SMEM_GEMM>>>(yth, ytl, whT, wlT, bias, out);
}

// round 10
// speedup vs baseline: 1.2641x; 1.2641x over previous
#include <cuda_runtime.h>
#include <cuda_bf16.h>
#include <math.h>
#include <stdint.h>

#define BB 16
#define LL 1024
#define HH 1024
#define NN 64

typedef __nv_bfloat16 bf16;

// scratch (device globals — no allocation allowed)
__device__ float g_kern[HH * LL];              // kern [h][l]
__device__ bf16 g_xth[HH * BB * LL];           // x^T hi [h][b][l]
__device__ bf16 g_xtl[HH * BB * LL];           // x^T lo
__device__ bf16 g_yth[HH * BB * LL];           // y^T hi [h][b*l] (k-major for GEMM)
__device__ bf16 g_ytl[HH * BB * LL];           // y^T lo
__device__ bf16 g_whT[2048 * 1024];            // W^T hi [n][k]
__device__ bf16 g_wlT[2048 * 1024];            // W^T lo [n][k]

// ---- helpers ----------------------------------------------------------------
__device__ __forceinline__ uint32_t smem_u32(const void* p) {
    uint32_t a;
    asm("{ .reg .u64 t; cvta.to.shared.u64 t, %1; cvt.u32.u64 %0, t; }"
        : "=r"(a) : "l"(p));
    return a;
}
#define CP_ASYNC16(dst, src) \
    asm volatile("cp.async.cg.shared.global [%0], [%1], 16;" :: "r"(dst), "l"(src))
#define CP_COMMIT() asm volatile("cp.async.commit_group;" ::: "memory")
#define CP_WAIT2() asm volatile("cp.async.wait_group 2;" ::: "memory")
#define CP_WAIT1() asm volatile("cp.async.wait_group 1;" ::: "memory")
#define CP_WAIT0() asm volatile("cp.async.wait_group 0;" ::: "memory")

__device__ __forceinline__ void ldsm_x4(uint32_t* r, uint32_t addr) {
    asm volatile("ldmatrix.sync.aligned.m8n8.x4.shared.b16 {%0,%1,%2,%3}, [%4];"
                 : "=r"(r[0]), "=r"(r[1]), "=r"(r[2]), "=r"(r[3]) : "r"(addr));
}
__device__ __forceinline__ void ldsm_x4t(uint32_t* r, uint32_t addr) {
    asm volatile("ldmatrix.sync.aligned.m8n8.x4.trans.shared.b16 {%0,%1,%2,%3}, [%4];"
                 : "=r"(r[0]), "=r"(r[1]), "=r"(r[2]), "=r"(r[3]) : "r"(addr));
}
__device__ __forceinline__ void mma_bf16(float* c, const uint32_t* a,
                                         const uint32_t* b) {
    asm volatile(
        "mma.sync.aligned.m16n8k16.row.col.f32.bf16.bf16.f32 "
        "{%0,%1,%2,%3}, {%4,%5,%6,%7}, {%8,%9}, {%0,%1,%2,%3};"
        : "+f"(c[0]), "+f"(c[1]), "+f"(c[2]), "+f"(c[3])
        : "r"(a[0]), "r"(a[1]), "r"(a[2]), "r"(a[3]), "r"(b[0]), "r"(b[1]));
}
__device__ __forceinline__ float gelu_tanh(float t) {
    float c = 0.7978845608028654f * (t + 0.044715f * t * t * t);
    return 0.5f * t * (1.0f + tanhf(c));
}

// ---------------------------------------------------------------------------
// Kernel 1: S4D kernel generation, L-chunked (8 chunks of 128 per h).
// ---------------------------------------------------------------------------
#define GCH 128

__global__ void k_gen(const float* __restrict__ log_dt,
                      const float* __restrict__ Arl,
                      const float* __restrict__ Aim,
                      const float* __restrict__ Cr,
                      const float* __restrict__ Ci,
                      float* __restrict__ kern) {
    int h = blockIdx.x;
    int l0 = blockIdx.y * GCH;
    int lane = threadIdx.x;
    float dt = expf(log_dt[h]);

    float zr[2], zi[2], wr[2], wi[2];
#pragma unroll
    for (int t = 0; t < 2; t++) {
        int n = lane + t * 32;
        float ar = -expf(Arl[h * NN + n]);
        float ai = Aim[h * NN + n];
        float dr = dt * ar, di = dt * ai;
        float er = expf(dr);
        float sn, cs;
        sincosf(di, &sn, &cs);
        float Er = er * cs - 1.0f, Ei = er * sn;
        float inv = 1.0f / (ar * ar + ai * ai);
        float Fr = (Er * ar + Ei * ai) * inv;
        float Fi = (Ei * ar - Er * ai) * inv;
        float cr = Cr[h * NN + n], ci = Ci[h * NN + n];
        float c0r = cr * Fr - ci * Fi;
        float c0i = cr * Fi + ci * Fr;
        float e0 = expf(dr * (float)l0);
        float s0, q0;
        sincosf(di * (float)l0, &s0, &q0);
        float pr = e0 * q0, pi = e0 * s0;
        zr[t] = c0r * pr - c0i * pi;
        zi[t] = c0r * pi + c0i * pr;
        wr[t] = er * cs;
        wi[t] = er * sn;
    }
    float* kout = kern + (size_t)h * LL + l0;
    for (int l = 0; l < GCH; l++) {
        float s = zr[0] + zr[1];
#pragma unroll
        for (int o = 16; o > 0; o >>= 1)
            s += __shfl_xor_sync(0xffffffffu, s, o);
        if (lane == 0) kout[l] = 2.0f * s;
#pragma unroll
        for (int t = 0; t < 2; t++) {
            float tr = zr[t] * wr[t] - zi[t] * wi[t];
            zi[t] = zr[t] * wi[t] + zi[t] * wr[t];
            zr[t] = tr;
        }
    }
}

// ---------------------------------------------------------------------------
// Kernel 1b: W [1024,2048] -> W^T bf16 hi/lo [2048][1024]
// ---------------------------------------------------------------------------
__global__ void k_prepW(const float* __restrict__ W,
                        bf16* __restrict__ whT, bf16* __restrict__ wlT) {
    __shared__ float t[32][33];
    int tx = threadIdx.x, ty = threadIdx.y;
    int n0 = blockIdx.x * 32, k0 = blockIdx.y * 32;
#pragma unroll
    for (int i = 0; i < 4; i++)
        t[ty + i * 8][tx] = W[(size_t)(k0 + ty + i * 8) * 2048 + n0 + tx];
    __syncthreads();
#pragma unroll
    for (int i = 0; i < 4; i++) {
        int n = n0 + ty + i * 8;
        float v = t[tx][ty + i * 8];
        bf16 h = __float2bfloat16(v);
        float lo = v - __bfloat162float(h);
        whT[(size_t)n * 1024 + k0 + tx] = h;
        wlT[(size_t)n * 1024 + k0 + tx] = __float2bfloat16(lo);
    }
}

// ---------------------------------------------------------------------------
// Kernel 1c: x [b][l][h] f32 -> x^T bf16 hi/lo [h][b][l]
// ---------------------------------------------------------------------------
__global__ void k_xt(const float* __restrict__ x,
                     bf16* __restrict__ xth, bf16* __restrict__ xtl) {
    __shared__ float t[32][33];
    int tx = threadIdx.x, ty = threadIdx.y;
    int l0 = blockIdx.x * 32, h0 = blockIdx.y * 32, b = blockIdx.z;
    const float* xb = x + (size_t)b * LL * HH;
#pragma unroll
    for (int i = 0; i < 4; i++)
        t[ty + i * 8][tx] = xb[(size_t)(l0 + ty + i * 8) * HH + h0 + tx];
    __syncthreads();
#pragma unroll
    for (int i = 0; i < 4; i++) {
        int hh = ty + i * 8;
        float v = t[tx][hh];
        bf16 hi = __float2bfloat16(v);
        float lo = v - __bfloat162float(hi);
        size_t o = (size_t)(h0 + hh) * (BB * LL) + (size_t)b * LL + l0 + tx;
        xth[o] = hi;
        xtl[o] = __float2bfloat16(lo);
    }
}

// ---------------------------------------------------------------------------
// Kernel 2: Toeplitz tensor-core causal conv + D-skip + gelu.
// EXACT R6 structure (regs 135, measured 261us). ONLY change vs R6/R8:
// __launch_bounds__(256, 2) -> 2 CTAs/SM (regs capped at 128; smem
// 2 x 104.5KB = 209KB fits the 228KB carveout) for latency hiding.
// ---------------------------------------------------------------------------
#define XP 2064
#define TP 144
#define SM_XH 0
#define SM_XL 33024
#define SM_K  66048
#define SM_T  70144
#define TBUF  18432
#define SMEM_CONV 107008

__global__ __launch_bounds__(256, 2) void k_conv_tc(
    const bf16* __restrict__ xth, const bf16* __restrict__ xtl,
    const float* __restrict__ kern, const float* __restrict__ D,
    bf16* __restrict__ yth, bf16* __restrict__ ytl) {
    extern __shared__ __align__(128) char smem[];
    uint32_t sb = smem_u32(smem);
    int tid = threadIdx.x;
    int wid = tid >> 5;
    int lane = tid & 31;
    int h = blockIdx.x;

#pragma unroll
    for (int m = 0; m < 2; m++) {
        const bf16* s0 = (m ? xtl : xth) + (size_t)h * (BB * LL);
        uint32_t d0 = sb + (m ? SM_XL : SM_XH);
        for (int i = tid; i < 2048; i += 256) {
            int b = i >> 7, g = i & 127;
            CP_ASYNC16(d0 + b * XP + g * 16, s0 + (size_t)b * LL + g * 8);
        }
    }
    CP_COMMIT();

    float* ks = (float*)(smem + SM_K);
    for (int i = tid; i < 1024; i += 256) ks[i] = kern[(size_t)h * LL + i];
    __syncthreads();

    for (int i = tid; i < 4096; i += 256) {
        int r = i >> 6, c = i & 63;
        int off = r - c;
        float v = (off >= 0) ? ks[off] : 0.0f;
        bf16 hi = __float2bfloat16(v);
        bf16 lo = __float2bfloat16(v - __bfloat162float(hi));
        *(bf16*)(smem + SM_T + r * TP + c * 2) = hi;
        *(bf16*)(smem + SM_T + 9216 + r * TP + c * 2) = lo;
    }
    CP_WAIT0();
    __syncthreads();

    float acc[2][4][2][4];
#pragma unroll
    for (int t = 0; t < 2; t++)
#pragma unroll
        for (int mf = 0; mf < 4; mf++)
#pragma unroll
            for (int nf = 0; nf < 2; nf++)
#pragma unroll
                for (int e = 0; e < 4; e++) acc[t][mf][nf][e] = 0.0f;

#pragma unroll 1
    for (int d = 0; d < 16; d++) {
        int bufT = d & 1;
        if (d > 0) {
            __syncthreads();
            for (int i = tid; i < 4096; i += 256) {
                int r = i >> 6, c = i & 63;
                float v = ks[d * 64 + r - c];
                bf16 hi = __float2bfloat16(v);
                bf16 lo = __float2bfloat16(v - __bfloat162float(hi));
                *(bf16*)(smem + SM_T + bufT * TBUF + r * TP + c * 2) = hi;
                *(bf16*)(smem + SM_T + bufT * TBUF + 9216 + r * TP + c * 2) = lo;
            }
            __syncthreads();
        }
        uint32_t tH = sb + SM_T + bufT * TBUF;
        uint32_t tL = tH + 9216;
#pragma unroll
        for (int t = 0; t < 2; t++) {
            int li = t ? (15 - wid) : wid;
            if (li < d) continue;
            int ji = li - d;
#pragma unroll
            for (int kc = 0; kc < 4; kc++) {
                uint32_t a_h[4][4], a_l[4][4];
                uint32_t arow = (lane & 15) * TP + kc * 32 + (lane >> 4) * 16;
#pragma unroll
                for (int mf = 0; mf < 4; mf++) {
                    ldsm_x4(a_h[mf], tH + mf * 16 * TP + arow);
                    ldsm_x4(a_l[mf], tL + mf * 16 * TP + arow);
                }
                uint32_t bh[2][2], bl[2][2];
                uint32_t boff = (((lane >> 4) & 1) * 8 + (lane & 7)) * XP +
                                ji * 128 + kc * 32 + ((lane >> 3) & 1) * 16;
                {
                    uint32_t t4[4];
                    ldsm_x4(t4, sb + SM_XH + boff);
                    bh[0][0] = t4[0]; bh[0][1] = t4[1];
                    bh[1][0] = t4[2]; bh[1][1] = t4[3];
                    ldsm_x4(t4, sb + SM_XL + boff);
                    bl[0][0] = t4[0]; bl[0][1] = t4[1];
                    bl[1][0] = t4[2]; bl[1][1] = t4[3];
                }
#pragma unroll
                for (int mf = 0; mf < 4; mf++)
#pragma unroll
                    for (int nf = 0; nf < 2; nf++) {
                        mma_bf16(acc[t][mf][nf], a_h[mf], bh[nf]);
                        mma_bf16(acc[t][mf][nf], a_h[mf], bl[nf]);
                        mma_bf16(acc[t][mf][nf], a_l[mf], bh[nf]);
                    }
            }
        }
    }

    __syncthreads();
    float Dh = D[h];
    float* epf = (float*)(smem + SM_T + wid * 4352);
#pragma unroll 1
    for (int t = 0; t < 2; t++) {
        int li = t ? (15 - wid) : wid;
        int r0 = lane >> 2, cc = (lane & 3) * 2;
#pragma unroll
        for (int mf = 0; mf < 4; mf++)
#pragma unroll
            for (int nf = 0; nf < 2; nf++) {
                int bq = nf * 8 + cc;
                int lq = mf * 16 + r0;
                epf[bq * 68 + lq]           = acc[t][mf][nf][0];
                epf[(bq + 1) * 68 + lq]     = acc[t][mf][nf][1];
                epf[bq * 68 + lq + 8]       = acc[t][mf][nf][2];
                epf[(bq + 1) * 68 + lq + 8] = acc[t][mf][nf][3];
            }
        __syncwarp();
#pragma unroll
        for (int i = lane; i < 1024; i += 32) {
            int b = i >> 6, l = i & 63;
            int lout = li * 64 + l;
            float xv = __bfloat162float(*(bf16*)(smem + SM_XH + b * XP + lout * 2)) +
                       __bfloat162float(*(bf16*)(smem + SM_XL + b * XP + lout * 2));
            float v = gelu_tanh(epf[b * 68 + l] + xv * Dh);
            bf16 hi = __float2bfloat16(v);
            bf16 lo = __float2bfloat16(v - __bfloat162float(hi));
            size_t o = (size_t)h * (BB * LL) + (size_t)b * LL + lout;
            yth[o] = hi;
            ytl[o] = lo;
        }
        __syncwarp();
    }
}

// ---------------------------------------------------------------------------
// Kernel 3: mma.sync bf16x3 GEMM + bias + GLU. 3-stage cp.async pipeline.
// (unchanged from R8)
// ---------------------------------------------------------------------------
#define GAP 272
#define GABUF (32 * GAP)
#define GBP 80
#define GBBUF (256 * GBP)
#define SM_GA 0
#define SM_GB 52224
#define SMEM_GEMM 175104
#define GNS 32

__global__ __launch_bounds__(256, 1) void k_gemm_mma(
    const bf16* __restrict__ Yth, const bf16* __restrict__ Ytl,
    const bf16* __restrict__ WhT, const bf16* __restrict__ WlT,
    const float* __restrict__ bias, float* __restrict__ out) {
    extern __shared__ __align__(128) char smem[];
    uint32_t sb = smem_u32(smem);
    int tid = threadIdx.x;
    int wid = tid >> 5;
    int lane = tid & 31;
    int wm = wid >> 2;
    int wn = wid & 3;
    int N0a = blockIdx.x * 128;
    int M0 = blockIdx.y * 128;

    float acc[4][8][4];
#pragma unroll
    for (int i = 0; i < 4; i++)
#pragma unroll
        for (int j = 0; j < 8; j++)
#pragma unroll
            for (int e = 0; e < 4; e++) acc[i][j][e] = 0.0f;

#define G_ISSUE(S)                                                              \
    {                                                                           \
        int _s = (S);                                                           \
        int _buf = _s % 3;                                                      \
        int K0 = _s * 32;                                                       \
        _Pragma("unroll") for (int it = 0; it < 12; it++) {                     \
            int i = tid + it * 256;                                             \
            const bf16* src;                                                    \
            uint32_t dst;                                                       \
            if (i < 1024) {                                                     \
                int mat = i >> 9, r = (i >> 4) & 31, g = i & 15;                \
                src = (mat ? Ytl : Yth) + (size_t)(K0 + r) * 16384 + M0 + g * 8;\
                dst = sb + SM_GA + (_buf * 2 + mat) * GABUF + r * GAP + g * 16; \
            } else {                                                            \
                int j = i - 1024;                                               \
                int mat = j >> 10, r = (j >> 2) & 255, g = j & 3;               \
                int n = (r & 1) ? (1024 + N0a + (r >> 1)) : (N0a + (r >> 1));   \
                src = (mat ? WlT : WhT) + (size_t)n * 1024 + K0 + g * 8;        \
                dst = sb + SM_GB + (_buf * 2 + mat) * GBBUF + r * GBP + g * 16; \
            }                                                                   \
            CP_ASYNC16(dst, src);                                               \
        }                                                                       \
        CP_COMMIT();                                                            \
    }

    G_ISSUE(0);
    G_ISSUE(1);
#pragma unroll 1
    for (int s = 0; s < GNS; s++) {
        int buf = s % 3;
        if (s + 2 < GNS) {
            G_ISSUE(s + 2);
            CP_WAIT2();
        } else if (s + 1 < GNS) {
            CP_WAIT1();
        } else {
            CP_WAIT0();
        }
        __syncthreads();

        uint32_t aHb = sb + SM_GA + (buf * 2 + 0) * GABUF;
        uint32_t aLb = sb + SM_GA + (buf * 2 + 1) * GABUF;
        uint32_t bHb = sb + SM_GB + (buf * 2 + 0) * GBBUF;
        uint32_t bLb = sb + SM_GB + (buf * 2 + 1) * GBBUF;

#pragma unroll
        for (int kc = 0; kc < 2; kc++) {
            uint32_t a_h[4][4], a_l[4][4];
            uint32_t arow = (kc * 16 + ((lane >> 4) & 1) * 8 + (lane & 7)) * GAP;
#pragma unroll
            for (int mf = 0; mf < 4; mf++) {
                uint32_t ao = arow + (wm * 64 + mf * 16 + ((lane >> 3) & 1) * 8) * 2;
                ldsm_x4t(a_h[mf], aHb + ao);
                ldsm_x4t(a_l[mf], aLb + ao);
            }
            uint32_t boff = (((lane >> 4) & 1) * 8 + (lane & 7)) * GBP +
                            kc * 32 + ((lane >> 3) & 1) * 16;
#pragma unroll
            for (int q = 0; q < 4; q++) {
                uint32_t badr = (wn * 64 + q * 16) * GBP + boff;
                uint32_t bh[2][2], bl[2][2];
                uint32_t t4[4];
                ldsm_x4(t4, bHb + badr);
                bh[0][0] = t4[0]; bh[0][1] = t4[1];
                bh[1][0] = t4[2]; bh[1][1] = t4[3];
                ldsm_x4(t4, bLb + badr);
                bl[0][0] = t4[0]; bl[0][1] = t4[1];
                bl[1][0] = t4[2]; bl[1][1] = t4[3];
#pragma unroll
                for (int mf = 0; mf < 4; mf++)
#pragma unroll
                    for (int e = 0; e < 2; e++) {
                        int nf = 2 * q + e;
                        mma_bf16(acc[mf][nf], a_h[mf], bh[e]);
                        mma_bf16(acc[mf][nf], a_h[mf], bl[e]);
                        mma_bf16(acc[mf][nf], a_l[mf], bh[e]);
                    }
            }
        }
        __syncthreads();
    }

#pragma unroll
    for (int nf = 0; nf < 8; nf++) {
        int p = wn * 32 + nf * 4 + (lane & 3);
        int col = N0a + p;
        float ba = bias[col];
        float bg = bias[1024 + col];
#pragma unroll
        for (int mf = 0; mf < 4; mf++) {
            int m = M0 + wm * 64 + mf * 16 + (lane >> 2);
            float a0 = acc[mf][nf][0] + ba;
            float g0 = acc[mf][nf][1] + bg;
            float a1 = acc[mf][nf][2] + ba;
            float g1 = acc[mf][nf][3] + bg;
            out[(size_t)m * 1024 + col]       = a0 / (1.0f + expf(-g0));
            out[(size_t)(m + 8) * 1024 + col] = a1 / (1.0f + expf(-g1));
        }
    }
}

// ---------------------------------------------------------------------------
extern "C" void kernel_launch(void* const* d_in, const int* in_sizes, int n_in,
                              void* d_out, int out_size) {
    const float* x      = (const float*)d_in[0];
    const float* log_dt = (const float*)d_in[1];
    const float* Arl    = (const float*)d_in[2];
    const float* Aim    = (const float*)d_in[3];
    const float* Cr     = (const float*)d_in[4];
    const float* Ci     = (const float*)d_in[5];
    const float* D      = (const float*)d_in[6];
    const float* W      = (const float*)d_in[7];
    const float* bias   = (const float*)d_in[8];
    float* out = (float*)d_out;

    float* kern;
    bf16 *xth, *xtl, *yth, *ytl, *whT, *wlT;
    cudaGetSymbolAddress((void**)&kern, g_kern);
    cudaGetSymbolAddress((void**)&xth, g_xth);
    cudaGetSymbolAddress((void**)&xtl, g_xtl);
    cudaGetSymbolAddress((void**)&yth, g_yth);
    cudaGetSymbolAddress((void**)&ytl, g_ytl);
    cudaGetSymbolAddress((void**)&whT, g_whT);
    cudaGetSymbolAddress((void**)&wlT, g_wlT);

    cudaFuncSetAttribute(k_conv_tc, cudaFuncAttributeMaxDynamicSharedMemorySize,
                         SMEM_CONV);
    cudaFuncSetAttribute(k_gemm_mma, cudaFuncAttributeMaxDynamicSharedMemorySize,
                         SMEM_GEMM);

    k_gen<<<dim3(HH, LL / GCH), 32>>>(log_dt, Arl, Aim, Cr, Ci, kern);
    k_prepW<<<dim3(2048 / 32, 1024 / 32), dim3(32, 8)>>>(W, whT, wlT);
    k_xt<<<dim3(LL / 32, HH / 32, BB), dim3(32, 8)>>>(x, xth, xtl);

    k_conv_tc<<<HH, 256, SMEM_CONV>>>(xth, xtl, kern, D, yth, ytl);

    dim3 ggrid(2048 / 256, 16384 / 128);   // (8, 128)
    k_gemm_mma<<<ggrid, 256, SMEM_GEMM>>>(yth, ytl, whT, wlT, bias, out);
}

// round 11
// speedup vs baseline: 1.3532x; 1.0705x over previous
#include <cuda_runtime.h>
#include <cuda_bf16.h>
#include <math.h>
#include <stdint.h>

#define BB 16
#define LL 1024
#define HH 1024
#define NN 64

typedef __nv_bfloat16 bf16;

// scratch (device globals — no allocation allowed)
__device__ float g_kern[HH * LL];              // kern [h][l]
__device__ bf16 g_xth[HH * BB * LL];           // x^T hi [h][b][l]
__device__ bf16 g_xtl[HH * BB * LL];           // x^T lo
__device__ bf16 g_yth[HH * BB * LL];           // y^T hi [h][b*l] (k-major for GEMM)
__device__ bf16 g_ytl[HH * BB * LL];           // y^T lo
__device__ bf16 g_whT[2048 * 1024];            // W^T hi [n][k]
__device__ bf16 g_wlT[2048 * 1024];            // W^T lo [n][k]

// ---- helpers ----------------------------------------------------------------
__device__ __forceinline__ uint32_t smem_u32(const void* p) {
    uint32_t a;
    asm("{ .reg .u64 t; cvta.to.shared.u64 t, %1; cvt.u32.u64 %0, t; }"
        : "=r"(a) : "l"(p));
    return a;
}
#define CP_ASYNC16(dst, src) \
    asm volatile("cp.async.cg.shared.global [%0], [%1], 16;" :: "r"(dst), "l"(src))
#define CP_COMMIT() asm volatile("cp.async.commit_group;" ::: "memory")
#define CP_WAIT1() asm volatile("cp.async.wait_group 1;" ::: "memory")
#define CP_WAIT0() asm volatile("cp.async.wait_group 0;" ::: "memory")

__device__ __forceinline__ void ldsm_x4(uint32_t* r, uint32_t addr) {
    asm volatile("ldmatrix.sync.aligned.m8n8.x4.shared.b16 {%0,%1,%2,%3}, [%4];"
                 : "=r"(r[0]), "=r"(r[1]), "=r"(r[2]), "=r"(r[3]) : "r"(addr));
}
__device__ __forceinline__ void ldsm_x4t(uint32_t* r, uint32_t addr) {
    asm volatile("ldmatrix.sync.aligned.m8n8.x4.trans.shared.b16 {%0,%1,%2,%3}, [%4];"
                 : "=r"(r[0]), "=r"(r[1]), "=r"(r[2]), "=r"(r[3]) : "r"(addr));
}
__device__ __forceinline__ void mma_bf16(float* c, const uint32_t* a,
                                         const uint32_t* b) {
    asm volatile(
        "mma.sync.aligned.m16n8k16.row.col.f32.bf16.bf16.f32 "
        "{%0,%1,%2,%3}, {%4,%5,%6,%7}, {%8,%9}, {%0,%1,%2,%3};"
        : "+f"(c[0]), "+f"(c[1]), "+f"(c[2]), "+f"(c[3])
        : "r"(a[0]), "r"(a[1]), "r"(a[2]), "r"(a[3]), "r"(b[0]), "r"(b[1]));
}
__device__ __forceinline__ float gelu_tanh(float t) {
    float c = 0.7978845608028654f * (t + 0.044715f * t * t * t);
    return 0.5f * t * (1.0f + tanhf(c));
}

// ---------------------------------------------------------------------------
// Kernel 1: S4D kernel generation, L-chunked (8 chunks of 128 per h).
// ---------------------------------------------------------------------------
#define GCH 128

__global__ void k_gen(const float* __restrict__ log_dt,
                      const float* __restrict__ Arl,
                      const float* __restrict__ Aim,
                      const float* __restrict__ Cr,
                      const float* __restrict__ Ci,
                      float* __restrict__ kern) {
    int h = blockIdx.x;
    int l0 = blockIdx.y * GCH;
    int lane = threadIdx.x;
    float dt = expf(log_dt[h]);

    float zr[2], zi[2], wr[2], wi[2];
#pragma unroll
    for (int t = 0; t < 2; t++) {
        int n = lane + t * 32;
        float ar = -expf(Arl[h * NN + n]);
        float ai = Aim[h * NN + n];
        float dr = dt * ar, di = dt * ai;
        float er = expf(dr);
        float sn, cs;
        sincosf(di, &sn, &cs);
        float Er = er * cs - 1.0f, Ei = er * sn;
        float inv = 1.0f / (ar * ar + ai * ai);
        float Fr = (Er * ar + Ei * ai) * inv;
        float Fi = (Ei * ar - Er * ai) * inv;
        float cr = Cr[h * NN + n], ci = Ci[h * NN + n];
        float c0r = cr * Fr - ci * Fi;
        float c0i = cr * Fi + ci * Fr;
        float e0 = expf(dr * (float)l0);
        float s0, q0;
        sincosf(di * (float)l0, &s0, &q0);
        float pr = e0 * q0, pi = e0 * s0;
        zr[t] = c0r * pr - c0i * pi;
        zi[t] = c0r * pi + c0i * pr;
        wr[t] = er * cs;
        wi[t] = er * sn;
    }
    float* kout = kern + (size_t)h * LL + l0;
    for (int l = 0; l < GCH; l++) {
        float s = zr[0] + zr[1];
#pragma unroll
        for (int o = 16; o > 0; o >>= 1)
            s += __shfl_xor_sync(0xffffffffu, s, o);
        if (lane == 0) kout[l] = 2.0f * s;
#pragma unroll
        for (int t = 0; t < 2; t++) {
            float tr = zr[t] * wr[t] - zi[t] * wi[t];
            zi[t] = zr[t] * wi[t] + zi[t] * wr[t];
            zr[t] = tr;
        }
    }
}

// ---------------------------------------------------------------------------
// Kernel 1b: W [1024,2048] -> W^T bf16 hi/lo [2048][1024]
// ---------------------------------------------------------------------------
__global__ void k_prepW(const float* __restrict__ W,
                        bf16* __restrict__ whT, bf16* __restrict__ wlT) {
    __shared__ float t[32][33];
    int tx = threadIdx.x, ty = threadIdx.y;
    int n0 = blockIdx.x * 32, k0 = blockIdx.y * 32;
#pragma unroll
    for (int i = 0; i < 4; i++)
        t[ty + i * 8][tx] = W[(size_t)(k0 + ty + i * 8) * 2048 + n0 + tx];
    __syncthreads();
#pragma unroll
    for (int i = 0; i < 4; i++) {
        int n = n0 + ty + i * 8;
        float v = t[tx][ty + i * 8];
        bf16 h = __float2bfloat16(v);
        float lo = v - __bfloat162float(h);
        whT[(size_t)n * 1024 + k0 + tx] = h;
        wlT[(size_t)n * 1024 + k0 + tx] = __float2bfloat16(lo);
    }
}

// ---------------------------------------------------------------------------
// Kernel 1c: x [b][l][h] f32 -> x^T bf16 hi/lo [h][b][l]
// ---------------------------------------------------------------------------
__global__ void k_xt(const float* __restrict__ x,
                     bf16* __restrict__ xth, bf16* __restrict__ xtl) {
    __shared__ float t[32][33];
    int tx = threadIdx.x, ty = threadIdx.y;
    int l0 = blockIdx.x * 32, h0 = blockIdx.y * 32, b = blockIdx.z;
    const float* xb = x + (size_t)b * LL * HH;
#pragma unroll
    for (int i = 0; i < 4; i++)
        t[ty + i * 8][tx] = xb[(size_t)(l0 + ty + i * 8) * HH + h0 + tx];
    __syncthreads();
#pragma unroll
    for (int i = 0; i < 4; i++) {
        int hh = ty + i * 8;
        float v = t[tx][hh];
        bf16 hi = __float2bfloat16(v);
        float lo = v - __bfloat162float(hi);
        size_t o = (size_t)(h0 + hh) * (BB * LL) + (size_t)b * LL + l0 + tx;
        xth[o] = hi;
        xtl[o] = __float2bfloat16(lo);
    }
}

// ---------------------------------------------------------------------------
// Kernel 2: Toeplitz tensor-core causal conv + D-skip + gelu.
// (EXACT R10 winner: R6 structure + __launch_bounds__(256, 2).)
// ---------------------------------------------------------------------------
#define XP 2064
#define TP 144
#define SM_XH 0
#define SM_XL 33024
#define SM_K  66048
#define SM_T  70144
#define TBUF  18432
#define SMEM_CONV 107008

__global__ __launch_bounds__(256, 2) void k_conv_tc(
    const bf16* __restrict__ xth, const bf16* __restrict__ xtl,
    const float* __restrict__ kern, const float* __restrict__ D,
    bf16* __restrict__ yth, bf16* __restrict__ ytl) {
    extern __shared__ __align__(128) char smem[];
    uint32_t sb = smem_u32(smem);
    int tid = threadIdx.x;
    int wid = tid >> 5;
    int lane = tid & 31;
    int h = blockIdx.x;

#pragma unroll
    for (int m = 0; m < 2; m++) {
        const bf16* s0 = (m ? xtl : xth) + (size_t)h * (BB * LL);
        uint32_t d0 = sb + (m ? SM_XL : SM_XH);
        for (int i = tid; i < 2048; i += 256) {
            int b = i >> 7, g = i & 127;
            CP_ASYNC16(d0 + b * XP + g * 16, s0 + (size_t)b * LL + g * 8);
        }
    }
    CP_COMMIT();

    float* ks = (float*)(smem + SM_K);
    for (int i = tid; i < 1024; i += 256) ks[i] = kern[(size_t)h * LL + i];
    __syncthreads();

    for (int i = tid; i < 4096; i += 256) {
        int r = i >> 6, c = i & 63;
        int off = r - c;
        float v = (off >= 0) ? ks[off] : 0.0f;
        bf16 hi = __float2bfloat16(v);
        bf16 lo = __float2bfloat16(v - __bfloat162float(hi));
        *(bf16*)(smem + SM_T + r * TP + c * 2) = hi;
        *(bf16*)(smem + SM_T + 9216 + r * TP + c * 2) = lo;
    }
    CP_WAIT0();
    __syncthreads();

    float acc[2][4][2][4];
#pragma unroll
    for (int t = 0; t < 2; t++)
#pragma unroll
        for (int mf = 0; mf < 4; mf++)
#pragma unroll
            for (int nf = 0; nf < 2; nf++)
#pragma unroll
                for (int e = 0; e < 4; e++) acc[t][mf][nf][e] = 0.0f;

#pragma unroll 1
    for (int d = 0; d < 16; d++) {
        int bufT = d & 1;
        if (d > 0) {
            __syncthreads();
            for (int i = tid; i < 4096; i += 256) {
                int r = i >> 6, c = i & 63;
                float v = ks[d * 64 + r - c];
                bf16 hi = __float2bfloat16(v);
                bf16 lo = __float2bfloat16(v - __bfloat162float(hi));
                *(bf16*)(smem + SM_T + bufT * TBUF + r * TP + c * 2) = hi;
                *(bf16*)(smem + SM_T + bufT * TBUF + 9216 + r * TP + c * 2) = lo;
            }
            __syncthreads();
        }
        uint32_t tH = sb + SM_T + bufT * TBUF;
        uint32_t tL = tH + 9216;
#pragma unroll
        for (int t = 0; t < 2; t++) {
            int li = t ? (15 - wid) : wid;
            if (li < d) continue;
            int ji = li - d;
#pragma unroll
            for (int kc = 0; kc < 4; kc++) {
                uint32_t a_h[4][4], a_l[4][4];
                uint32_t arow = (lane & 15) * TP + kc * 32 + (lane >> 4) * 16;
#pragma unroll
                for (int mf = 0; mf < 4; mf++) {
                    ldsm_x4(a_h[mf], tH + mf * 16 * TP + arow);
                    ldsm_x4(a_l[mf], tL + mf * 16 * TP + arow);
                }
                uint32_t bh[2][2], bl[2][2];
                uint32_t boff = (((lane >> 4) & 1) * 8 + (lane & 7)) * XP +
                                ji * 128 + kc * 32 + ((lane >> 3) & 1) * 16;
                {
                    uint32_t t4[4];
                    ldsm_x4(t4, sb + SM_XH + boff);
                    bh[0][0] = t4[0]; bh[0][1] = t4[1];
                    bh[1][0] = t4[2]; bh[1][1] = t4[3];
                    ldsm_x4(t4, sb + SM_XL + boff);
                    bl[0][0] = t4[0]; bl[0][1] = t4[1];
                    bl[1][0] = t4[2]; bl[1][1] = t4[3];
                }
#pragma unroll
                for (int mf = 0; mf < 4; mf++)
#pragma unroll
                    for (int nf = 0; nf < 2; nf++) {
                        mma_bf16(acc[t][mf][nf], a_h[mf], bh[nf]);
                        mma_bf16(acc[t][mf][nf], a_h[mf], bl[nf]);
                        mma_bf16(acc[t][mf][nf], a_l[mf], bh[nf]);
                    }
            }
        }
    }

    __syncthreads();
    float Dh = D[h];
    float* epf = (float*)(smem + SM_T + wid * 4352);
#pragma unroll 1
    for (int t = 0; t < 2; t++) {
        int li = t ? (15 - wid) : wid;
        int r0 = lane >> 2, cc = (lane & 3) * 2;
#pragma unroll
        for (int mf = 0; mf < 4; mf++)
#pragma unroll
            for (int nf = 0; nf < 2; nf++) {
                int bq = nf * 8 + cc;
                int lq = mf * 16 + r0;
                epf[bq * 68 + lq]           = acc[t][mf][nf][0];
                epf[(bq + 1) * 68 + lq]     = acc[t][mf][nf][1];
                epf[bq * 68 + lq + 8]       = acc[t][mf][nf][2];
                epf[(bq + 1) * 68 + lq + 8] = acc[t][mf][nf][3];
            }
        __syncwarp();
#pragma unroll
        for (int i = lane; i < 1024; i += 32) {
            int b = i >> 6, l = i & 63;
            int lout = li * 64 + l;
            float xv = __bfloat162float(*(bf16*)(smem + SM_XH + b * XP + lout * 2)) +
                       __bfloat162float(*(bf16*)(smem + SM_XL + b * XP + lout * 2));
            float v = gelu_tanh(epf[b * 68 + l] + xv * Dh);
            bf16 hi = __float2bfloat16(v);
            bf16 lo = __float2bfloat16(v - __bfloat162float(hi));
            size_t o = (size_t)h * (BB * LL) + (size_t)b * LL + lout;
            yth[o] = hi;
            ytl[o] = lo;
        }
        __syncwarp();
    }
}

// ---------------------------------------------------------------------------
// Kernel 3: mma.sync bf16x3 GEMM + bias + GLU.
// NEW: 2 CTAs/SM. CTA tile 128m x 128 B-rows (64 out cols); 8 warps as
// 2m x 4n, warp tile 64m x 32 B-rows -> acc 64 regs/thread (fits 128 cap).
// 2-stage cp.async (3-stage measured neutral in R8). smem 75.8KB/CTA.
// ---------------------------------------------------------------------------
#define GAP 272                         // A smem pitch (128 m bf16 + 8 pad)
#define GABUF (32 * GAP)                // 8704
#define GBP 80                          // B smem pitch (32 k bf16 + 8 pad)
#define GBBUF (128 * GBP)               // 10240
#define SM_GA 0                         // [2 buf][2 mat][GABUF] = 34816
#define SM_GB 34816                     // [2 buf][2 mat][GBBUF] = 40960
#define SMEM_GEMM 75776
#define GNS 32                          // K stages (1024/32)

__global__ __launch_bounds__(256, 2) void k_gemm_mma(
    const bf16* __restrict__ Yth, const bf16* __restrict__ Ytl,
    const bf16* __restrict__ WhT, const bf16* __restrict__ WlT,
    const float* __restrict__ bias, float* __restrict__ out) {
    extern __shared__ __align__(128) char smem[];
    uint32_t sb = smem_u32(smem);
    int tid = threadIdx.x;
    int wid = tid >> 5;
    int lane = tid & 31;
    int wm = wid >> 2;                  // 0/1 -> m half (64 each)
    int wn = wid & 3;                   // 0..3 -> 32 B-rows each
    int N0a = blockIdx.x * 64;          // 64 output cols per CTA
    int M0 = blockIdx.y * 128;

    float acc[4][4][4];
#pragma unroll
    for (int i = 0; i < 4; i++)
#pragma unroll
        for (int j = 0; j < 4; j++)
#pragma unroll
            for (int e = 0; e < 4; e++) acc[i][j][e] = 0.0f;

#define G_ISSUE(S)                                                              \
    {                                                                           \
        int _s = (S);                                                           \
        int _buf = _s & 1;                                                      \
        int K0 = _s * 32;                                                       \
        _Pragma("unroll") for (int it = 0; it < 8; it++) {                      \
            int i = tid + it * 256;                                             \
            const bf16* src;                                                    \
            uint32_t dst;                                                       \
            if (i < 1024) {                                                     \
                int mat = i >> 9, r = (i >> 4) & 31, g = i & 15;                \
                src = (mat ? Ytl : Yth) + (size_t)(K0 + r) * 16384 + M0 + g * 8;\
                dst = sb + SM_GA + (_buf * 2 + mat) * GABUF + r * GAP + g * 16; \
            } else {                                                            \
                int j = i - 1024;                                               \
                int mat = j >> 9, rr = (j >> 2) & 127, g = j & 3;               \
                int n = (rr & 1) ? (1024 + N0a + (rr >> 1)) : (N0a + (rr >> 1));\
                src = (mat ? WlT : WhT) + (size_t)n * 1024 + K0 + g * 8;        \
                dst = sb + SM_GB + (_buf * 2 + mat) * GBBUF + rr * GBP + g * 16;\
            }                                                                   \
            CP_ASYNC16(dst, src);                                               \
        }                                                                       \
        CP_COMMIT();                                                            \
    }

    G_ISSUE(0);
#pragma unroll 1
    for (int s = 0; s < GNS; s++) {
        int buf = s & 1;
        if (s + 1 < GNS) {
            G_ISSUE(s + 1);
            CP_WAIT1();
        } else {
            CP_WAIT0();
        }
        __syncthreads();

        uint32_t aHb = sb + SM_GA + (buf * 2 + 0) * GABUF;
        uint32_t aLb = sb + SM_GA + (buf * 2 + 1) * GABUF;
        uint32_t bHb = sb + SM_GB + (buf * 2 + 0) * GBBUF;
        uint32_t bLb = sb + SM_GB + (buf * 2 + 1) * GBBUF;

#pragma unroll
        for (int kc = 0; kc < 2; kc++) {
            // A fragments via trans-ldmatrix from [k][m] smem
            uint32_t a_h[4][4], a_l[4][4];
            uint32_t arow = (kc * 16 + ((lane >> 4) & 1) * 8 + (lane & 7)) * GAP;
#pragma unroll
            for (int mf = 0; mf < 4; mf++) {
                uint32_t ao = arow + (wm * 64 + mf * 16 + ((lane >> 3) & 1) * 8) * 2;
                ldsm_x4t(a_h[mf], aHb + ao);
                ldsm_x4t(a_l[mf], aLb + ao);
            }
            uint32_t boff = (((lane >> 4) & 1) * 8 + (lane & 7)) * GBP +
                            kc * 32 + ((lane >> 3) & 1) * 16;
#pragma unroll
            for (int q = 0; q < 2; q++) {
                uint32_t badr = (wn * 32 + q * 16) * GBP + boff;
                uint32_t bh[2][2], bl[2][2];
                uint32_t t4[4];
                ldsm_x4(t4, bHb + badr);
                bh[0][0] = t4[0]; bh[0][1] = t4[1];
                bh[1][0] = t4[2]; bh[1][1] = t4[3];
                ldsm_x4(t4, bLb + badr);
                bl[0][0] = t4[0]; bl[0][1] = t4[1];
                bl[1][0] = t4[2]; bl[1][1] = t4[3];
#pragma unroll
                for (int mf = 0; mf < 4; mf++)
#pragma unroll
                    for (int e = 0; e < 2; e++) {
                        int nf = 2 * q + e;
                        mma_bf16(acc[mf][nf], a_h[mf], bh[e]);
                        mma_bf16(acc[mf][nf], a_h[mf], bl[e]);
                        mma_bf16(acc[mf][nf], a_l[mf], bh[e]);
                    }
            }
        }
        __syncthreads();
    }

    // epilogue: bias + GLU (even B-row = a, odd = g, register-local pair)
#pragma unroll
    for (int nf = 0; nf < 4; nf++) {
        int p = wn * 16 + nf * 4 + (lane & 3);
        int col = N0a + p;
        float ba = bias[col];
        float bg = bias[1024 + col];
#pragma unroll
        for (int mf = 0; mf < 4; mf++) {
            int m = M0 + wm * 64 + mf * 16 + (lane >> 2);
            float a0 = acc[mf][nf][0] + ba;
            float g0 = acc[mf][nf][1] + bg;
            float a1 = acc[mf][nf][2] + ba;
            float g1 = acc[mf][nf][3] + bg;
            out[(size_t)m * 1024 + col]       = a0 / (1.0f + expf(-g0));
            out[(size_t)(m + 8) * 1024 + col] = a1 / (1.0f + expf(-g1));
        }
    }
}

// ---------------------------------------------------------------------------
extern "C" void kernel_launch(void* const* d_in, const int* in_sizes, int n_in,
                              void* d_out, int out_size) {
    const float* x      = (const float*)d_in[0];
    const float* log_dt = (const float*)d_in[1];
    const float* Arl    = (const float*)d_in[2];
    const float* Aim    = (const float*)d_in[3];
    const float* Cr     = (const float*)d_in[4];
    const float* Ci     = (const float*)d_in[5];
    const float* D      = (const float*)d_in[6];
    const float* W      = (const float*)d_in[7];
    const float* bias   = (const float*)d_in[8];
    float* out = (float*)d_out;

    float* kern;
    bf16 *xth, *xtl, *yth, *ytl, *whT, *wlT;
    cudaGetSymbolAddress((void**)&kern, g_kern);
    cudaGetSymbolAddress((void**)&xth, g_xth);
    cudaGetSymbolAddress((void**)&xtl, g_xtl);
    cudaGetSymbolAddress((void**)&yth, g_yth);
    cudaGetSymbolAddress((void**)&ytl, g_ytl);
    cudaGetSymbolAddress((void**)&whT, g_whT);
    cudaGetSymbolAddress((void**)&wlT, g_wlT);

    cudaFuncSetAttribute(k_conv_tc, cudaFuncAttributeMaxDynamicSharedMemorySize,
                         SMEM_CONV);
    cudaFuncSetAttribute(k_gemm_mma, cudaFuncAttributeMaxDynamicSharedMemorySize,
                         SMEM_GEMM);

    k_gen<<<dim3(HH, LL / GCH), 32>>>(log_dt, Arl, Aim, Cr, Ci, kern);
    k_prepW<<<dim3(2048 / 32, 1024 / 32), dim3(32, 8)>>>(W, whT, wlT);
    k_xt<<<dim3(LL / 32, HH / 32, BB), dim3(32, 8)>>>(x, xth, xtl);

    k_conv_tc<<<HH, 256, SMEM_CONV>>>(xth, xtl, kern, D, yth, ytl);

    dim3 ggrid(1024 / 64, 16384 / 128);   // (16, 128)
    k_gemm_mma<<<ggrid, 256, SMEM_GEMM>>>(yth, ytl, whT, wlT, bias, out);
}

// round 12
// speedup vs baseline: 1.6460x; 1.2163x over previous
#include <cuda_runtime.h>
#include <cuda_bf16.h>
#include <cuda_fp16.h>
#include <math.h>
#include <stdint.h>

#define BB 16
#define LL 1024
#define HH 1024
#define NN 64

typedef __nv_bfloat16 bf16;

// scratch (device globals — no allocation allowed)
__device__ float g_kern[HH * LL];              // kern [h][l]
__device__ bf16 g_xth[HH * BB * LL];           // x^T hi [h][b][l]
__device__ bf16 g_xtl[HH * BB * LL];           // x^T lo
__device__ __half g_yh[HH * BB * LL];          // y^T fp16 [h][b*l] (k-major for GEMM)
__device__ __half g_whT[2048 * 1024];          // W^T hi fp16 [n][k]
__device__ __half g_wlT[2048 * 1024];          // W^T lo fp16 [n][k]

// ---- helpers ----------------------------------------------------------------
__device__ __forceinline__ uint32_t smem_u32(const void* p) {
    uint32_t a;
    asm("{ .reg .u64 t; cvta.to.shared.u64 t, %1; cvt.u32.u64 %0, t; }"
        : "=r"(a) : "l"(p));
    return a;
}
#define CP_ASYNC16(dst, src) \
    asm volatile("cp.async.cg.shared.global [%0], [%1], 16;" :: "r"(dst), "l"(src))
#define CP_COMMIT() asm volatile("cp.async.commit_group;" ::: "memory")
#define CP_WAIT1() asm volatile("cp.async.wait_group 1;" ::: "memory")
#define CP_WAIT0() asm volatile("cp.async.wait_group 0;" ::: "memory")

__device__ __forceinline__ void ldsm_x4(uint32_t* r, uint32_t addr) {
    asm volatile("ldmatrix.sync.aligned.m8n8.x4.shared.b16 {%0,%1,%2,%3}, [%4];"
                 : "=r"(r[0]), "=r"(r[1]), "=r"(r[2]), "=r"(r[3]) : "r"(addr));
}
__device__ __forceinline__ void ldsm_x4t(uint32_t* r, uint32_t addr) {
    asm volatile("ldmatrix.sync.aligned.m8n8.x4.trans.shared.b16 {%0,%1,%2,%3}, [%4];"
                 : "=r"(r[0]), "=r"(r[1]), "=r"(r[2]), "=r"(r[3]) : "r"(addr));
}
__device__ __forceinline__ void mma_bf16(float* c, const uint32_t* a,
                                         const uint32_t* b) {
    asm volatile(
        "mma.sync.aligned.m16n8k16.row.col.f32.bf16.bf16.f32 "
        "{%0,%1,%2,%3}, {%4,%5,%6,%7}, {%8,%9}, {%0,%1,%2,%3};"
        : "+f"(c[0]), "+f"(c[1]), "+f"(c[2]), "+f"(c[3])
        : "r"(a[0]), "r"(a[1]), "r"(a[2]), "r"(a[3]), "r"(b[0]), "r"(b[1]));
}
__device__ __forceinline__ void mma_fp16(float* c, const uint32_t* a,
                                         const uint32_t* b) {
    asm volatile(
        "mma.sync.aligned.m16n8k16.row.col.f32.f16.f16.f32 "
        "{%0,%1,%2,%3}, {%4,%5,%6,%7}, {%8,%9}, {%0,%1,%2,%3};"
        : "+f"(c[0]), "+f"(c[1]), "+f"(c[2]), "+f"(c[3])
        : "r"(a[0]), "r"(a[1]), "r"(a[2]), "r"(a[3]), "r"(b[0]), "r"(b[1]));
}
__device__ __forceinline__ float gelu_tanh(float t) {
    float c = 0.7978845608028654f * (t + 0.044715f * t * t * t);
    return 0.5f * t * (1.0f + tanhf(c));
}

// ---------------------------------------------------------------------------
// Kernel 1: S4D kernel generation, L-chunked (8 chunks of 128 per h).
// ---------------------------------------------------------------------------
#define GCH 128

__global__ void k_gen(const float* __restrict__ log_dt,
                      const float* __restrict__ Arl,
                      const float* __restrict__ Aim,
                      const float* __restrict__ Cr,
                      const float* __restrict__ Ci,
                      float* __restrict__ kern) {
    int h = blockIdx.x;
    int l0 = blockIdx.y * GCH;
    int lane = threadIdx.x;
    float dt = expf(log_dt[h]);

    float zr[2], zi[2], wr[2], wi[2];
#pragma unroll
    for (int t = 0; t < 2; t++) {
        int n = lane + t * 32;
        float ar = -expf(Arl[h * NN + n]);
        float ai = Aim[h * NN + n];
        float dr = dt * ar, di = dt * ai;
        float er = expf(dr);
        float sn, cs;
        sincosf(di, &sn, &cs);
        float Er = er * cs - 1.0f, Ei = er * sn;
        float inv = 1.0f / (ar * ar + ai * ai);
        float Fr = (Er * ar + Ei * ai) * inv;
        float Fi = (Ei * ar - Er * ai) * inv;
        float cr = Cr[h * NN + n], ci = Ci[h * NN + n];
        float c0r = cr * Fr - ci * Fi;
        float c0i = cr * Fi + ci * Fr;
        float e0 = expf(dr * (float)l0);
        float s0, q0;
        sincosf(di * (float)l0, &s0, &q0);
        float pr = e0 * q0, pi = e0 * s0;
        zr[t] = c0r * pr - c0i * pi;
        zi[t] = c0r * pi + c0i * pr;
        wr[t] = er * cs;
        wi[t] = er * sn;
    }
    float* kout = kern + (size_t)h * LL + l0;
    for (int l = 0; l < GCH; l++) {
        float s = zr[0] + zr[1];
#pragma unroll
        for (int o = 16; o > 0; o >>= 1)
            s += __shfl_xor_sync(0xffffffffu, s, o);
        if (lane == 0) kout[l] = 2.0f * s;
#pragma unroll
        for (int t = 0; t < 2; t++) {
            float tr = zr[t] * wr[t] - zi[t] * wi[t];
            zi[t] = zr[t] * wi[t] + zi[t] * wr[t];
            zr[t] = tr;
        }
    }
}

// ---------------------------------------------------------------------------
// Kernel 1b: W [1024,2048] -> W^T fp16 hi/lo [2048][1024]
// ---------------------------------------------------------------------------
__global__ void k_prepW(const float* __restrict__ W,
                        __half* __restrict__ whT, __half* __restrict__ wlT) {
    __shared__ float t[32][33];
    int tx = threadIdx.x, ty = threadIdx.y;
    int n0 = blockIdx.x * 32, k0 = blockIdx.y * 32;
#pragma unroll
    for (int i = 0; i < 4; i++)
        t[ty + i * 8][tx] = W[(size_t)(k0 + ty + i * 8) * 2048 + n0 + tx];
    __syncthreads();
#pragma unroll
    for (int i = 0; i < 4; i++) {
        int n = n0 + ty + i * 8;
        float v = t[tx][ty + i * 8];
        __half h = __float2half(v);
        float lo = v - __half2float(h);
        whT[(size_t)n * 1024 + k0 + tx] = h;
        wlT[(size_t)n * 1024 + k0 + tx] = __float2half(lo);
    }
}

// ---------------------------------------------------------------------------
// Kernel 1c: x [b][l][h] f32 -> x^T bf16 hi/lo [h][b][l]
// ---------------------------------------------------------------------------
__global__ void k_xt(const float* __restrict__ x,
                     bf16* __restrict__ xth, bf16* __restrict__ xtl) {
    __shared__ float t[32][33];
    int tx = threadIdx.x, ty = threadIdx.y;
    int l0 = blockIdx.x * 32, h0 = blockIdx.y * 32, b = blockIdx.z;
    const float* xb = x + (size_t)b * LL * HH;
#pragma unroll
    for (int i = 0; i < 4; i++)
        t[ty + i * 8][tx] = xb[(size_t)(l0 + ty + i * 8) * HH + h0 + tx];
    __syncthreads();
#pragma unroll
    for (int i = 0; i < 4; i++) {
        int hh = ty + i * 8;
        float v = t[tx][hh];
        bf16 hi = __float2bfloat16(v);
        float lo = v - __bfloat162float(hi);
        size_t o = (size_t)(h0 + hh) * (BB * LL) + (size_t)b * LL + l0 + tx;
        xth[o] = hi;
        xtl[o] = __float2bfloat16(lo);
    }
}

// ---------------------------------------------------------------------------
// Kernel 2: Toeplitz tensor-core causal conv + D-skip + gelu.
// (R10 winner internally; epilogue now stores y as fp16, single copy.)
// ---------------------------------------------------------------------------
#define XP 2064
#define TP 144
#define SM_XH 0
#define SM_XL 33024
#define SM_K  66048
#define SM_T  70144
#define TBUF  18432
#define SMEM_CONV 107008

__global__ __launch_bounds__(256, 2) void k_conv_tc(
    const bf16* __restrict__ xth, const bf16* __restrict__ xtl,
    const float* __restrict__ kern, const float* __restrict__ D,
    __half* __restrict__ yh) {
    extern __shared__ __align__(128) char smem[];
    uint32_t sb = smem_u32(smem);
    int tid = threadIdx.x;
    int wid = tid >> 5;
    int lane = tid & 31;
    int h = blockIdx.x;

#pragma unroll
    for (int m = 0; m < 2; m++) {
        const bf16* s0 = (m ? xtl : xth) + (size_t)h * (BB * LL);
        uint32_t d0 = sb + (m ? SM_XL : SM_XH);
        for (int i = tid; i < 2048; i += 256) {
            int b = i >> 7, g = i & 127;
            CP_ASYNC16(d0 + b * XP + g * 16, s0 + (size_t)b * LL + g * 8);
        }
    }
    CP_COMMIT();

    float* ks = (float*)(smem + SM_K);
    for (int i = tid; i < 1024; i += 256) ks[i] = kern[(size_t)h * LL + i];
    __syncthreads();

    for (int i = tid; i < 4096; i += 256) {
        int r = i >> 6, c = i & 63;
        int off = r - c;
        float v = (off >= 0) ? ks[off] : 0.0f;
        bf16 hi = __float2bfloat16(v);
        bf16 lo = __float2bfloat16(v - __bfloat162float(hi));
        *(bf16*)(smem + SM_T + r * TP + c * 2) = hi;
        *(bf16*)(smem + SM_T + 9216 + r * TP + c * 2) = lo;
    }
    CP_WAIT0();
    __syncthreads();

    float acc[2][4][2][4];
#pragma unroll
    for (int t = 0; t < 2; t++)
#pragma unroll
        for (int mf = 0; mf < 4; mf++)
#pragma unroll
            for (int nf = 0; nf < 2; nf++)
#pragma unroll
                for (int e = 0; e < 4; e++) acc[t][mf][nf][e] = 0.0f;

#pragma unroll 1
    for (int d = 0; d < 16; d++) {
        int bufT = d & 1;
        if (d > 0) {
            __syncthreads();
            for (int i = tid; i < 4096; i += 256) {
                int r = i >> 6, c = i & 63;
                float v = ks[d * 64 + r - c];
                bf16 hi = __float2bfloat16(v);
                bf16 lo = __float2bfloat16(v - __bfloat162float(hi));
                *(bf16*)(smem + SM_T + bufT * TBUF + r * TP + c * 2) = hi;
                *(bf16*)(smem + SM_T + bufT * TBUF + 9216 + r * TP + c * 2) = lo;
            }
            __syncthreads();
        }
        uint32_t tH = sb + SM_T + bufT * TBUF;
        uint32_t tL = tH + 9216;
#pragma unroll
        for (int t = 0; t < 2; t++) {
            int li = t ? (15 - wid) : wid;
            if (li < d) continue;
            int ji = li - d;
#pragma unroll
            for (int kc = 0; kc < 4; kc++) {
                uint32_t a_h[4][4], a_l[4][4];
                uint32_t arow = (lane & 15) * TP + kc * 32 + (lane >> 4) * 16;
#pragma unroll
                for (int mf = 0; mf < 4; mf++) {
                    ldsm_x4(a_h[mf], tH + mf * 16 * TP + arow);
                    ldsm_x4(a_l[mf], tL + mf * 16 * TP + arow);
                }
                uint32_t bh[2][2], bl[2][2];
                uint32_t boff = (((lane >> 4) & 1) * 8 + (lane & 7)) * XP +
                                ji * 128 + kc * 32 + ((lane >> 3) & 1) * 16;
                {
                    uint32_t t4[4];
                    ldsm_x4(t4, sb + SM_XH + boff);
                    bh[0][0] = t4[0]; bh[0][1] = t4[1];
                    bh[1][0] = t4[2]; bh[1][1] = t4[3];
                    ldsm_x4(t4, sb + SM_XL + boff);
                    bl[0][0] = t4[0]; bl[0][1] = t4[1];
                    bl[1][0] = t4[2]; bl[1][1] = t4[3];
                }
#pragma unroll
                for (int mf = 0; mf < 4; mf++)
#pragma unroll
                    for (int nf = 0; nf < 2; nf++) {
                        mma_bf16(acc[t][mf][nf], a_h[mf], bh[nf]);
                        mma_bf16(acc[t][mf][nf], a_h[mf], bl[nf]);
                        mma_bf16(acc[t][mf][nf], a_l[mf], bh[nf]);
                    }
            }
        }
    }

    __syncthreads();
    float Dh = D[h];
    float* epf = (float*)(smem + SM_T + wid * 4352);
#pragma unroll 1
    for (int t = 0; t < 2; t++) {
        int li = t ? (15 - wid) : wid;
        int r0 = lane >> 2, cc = (lane & 3) * 2;
#pragma unroll
        for (int mf = 0; mf < 4; mf++)
#pragma unroll
            for (int nf = 0; nf < 2; nf++) {
                int bq = nf * 8 + cc;
                int lq = mf * 16 + r0;
                epf[bq * 68 + lq]           = acc[t][mf][nf][0];
                epf[(bq + 1) * 68 + lq]     = acc[t][mf][nf][1];
                epf[bq * 68 + lq + 8]       = acc[t][mf][nf][2];
                epf[(bq + 1) * 68 + lq + 8] = acc[t][mf][nf][3];
            }
        __syncwarp();
#pragma unroll
        for (int i = lane; i < 1024; i += 32) {
            int b = i >> 6, l = i & 63;
            int lout = li * 64 + l;
            float xv = __bfloat162float(*(bf16*)(smem + SM_XH + b * XP + lout * 2)) +
                       __bfloat162float(*(bf16*)(smem + SM_XL + b * XP + lout * 2));
            float v = gelu_tanh(epf[b * 68 + l] + xv * Dh);
            size_t o = (size_t)h * (BB * LL) + (size_t)b * LL + lout;
            yh[o] = __float2half(v);
        }
        __syncwarp();
    }
}

// ---------------------------------------------------------------------------
// Kernel 3: mma.sync fp16 2-term GEMM + bias + GLU.
// z = Yh*Wh + Yh*Wl (Yh = fp16(y); W fp16 hi/lo). 2 CTAs/SM, 2-stage pipe.
// CTA tile 128m x 128 B-rows (64 out cols, a/g interleaved); warp 64m x 32r.
// ---------------------------------------------------------------------------
#define GAP 272                         // A smem pitch (128 m fp16 + 8 pad)
#define GABUF (32 * GAP)                // 8704
#define GBP 80                          // B smem pitch (32 k fp16 + 8 pad)
#define GBBUF (128 * GBP)               // 10240
#define SM_GA 0                         // [2 buf][GABUF] = 17408
#define SM_GB 17408                     // [2 buf][2 mat][GBBUF] = 40960
#define SMEM_GEMM 58368
#define GNS 32                          // K stages (1024/32)

__global__ __launch_bounds__(256, 2) void k_gemm_mma(
    const __half* __restrict__ Yh,
    const __half* __restrict__ WhT, const __half* __restrict__ WlT,
    const float* __restrict__ bias, float* __restrict__ out) {
    extern __shared__ __align__(128) char smem[];
    uint32_t sb = smem_u32(smem);
    int tid = threadIdx.x;
    int wid = tid >> 5;
    int lane = tid & 31;
    int wm = wid >> 2;                  // 0/1 -> m half (64 each)
    int wn = wid & 3;                   // 0..3 -> 32 B-rows each
    int N0a = blockIdx.x * 64;          // 64 output cols per CTA
    int M0 = blockIdx.y * 128;

    float acc[4][4][4];
#pragma unroll
    for (int i = 0; i < 4; i++)
#pragma unroll
        for (int j = 0; j < 4; j++)
#pragma unroll
            for (int e = 0; e < 4; e++) acc[i][j][e] = 0.0f;

#define G_ISSUE(S)                                                              \
    {                                                                           \
        int _s = (S);                                                           \
        int _buf = _s & 1;                                                      \
        int K0 = _s * 32;                                                       \
        _Pragma("unroll") for (int it = 0; it < 6; it++) {                      \
            int i = tid + it * 256;                                             \
            const __half* src;                                                  \
            uint32_t dst;                                                       \
            if (i < 512) {                                                      \
                int r = i >> 4, g = i & 15;                                     \
                src = Yh + (size_t)(K0 + r) * 16384 + M0 + g * 8;               \
                dst = sb + SM_GA + _buf * GABUF + r * GAP + g * 16;             \
            } else {                                                            \
                int j = i - 512;                                                \
                int mat = j >> 9, rr = (j >> 2) & 127, g = j & 3;               \
                int n = (rr & 1) ? (1024 + N0a + (rr >> 1)) : (N0a + (rr >> 1));\
                src = (mat ? WlT : WhT) + (size_t)n * 1024 + K0 + g * 8;        \
                dst = sb + SM_GB + (_buf * 2 + mat) * GBBUF + rr * GBP + g * 16;\
            }                                                                   \
            CP_ASYNC16(dst, src);                                               \
        }                                                                       \
        CP_COMMIT();                                                            \
    }

    G_ISSUE(0);
#pragma unroll 1
    for (int s = 0; s < GNS; s++) {
        int buf = s & 1;
        if (s + 1 < GNS) {
            G_ISSUE(s + 1);
            CP_WAIT1();
        } else {
            CP_WAIT0();
        }
        __syncthreads();

        uint32_t aHb = sb + SM_GA + buf * GABUF;
        uint32_t bHb = sb + SM_GB + (buf * 2 + 0) * GBBUF;
        uint32_t bLb = sb + SM_GB + (buf * 2 + 1) * GBBUF;

#pragma unroll
        for (int kc = 0; kc < 2; kc++) {
            // A fragments via trans-ldmatrix from [k][m] smem (hi only)
            uint32_t a_h[4][4];
            uint32_t arow = (kc * 16 + ((lane >> 4) & 1) * 8 + (lane & 7)) * GAP;
#pragma unroll
            for (int mf = 0; mf < 4; mf++) {
                uint32_t ao = arow + (wm * 64 + mf * 16 + ((lane >> 3) & 1) * 8) * 2;
                ldsm_x4t(a_h[mf], aHb + ao);
            }
            uint32_t boff = (((lane >> 4) & 1) * 8 + (lane & 7)) * GBP +
                            kc * 32 + ((lane >> 3) & 1) * 16;
#pragma unroll
            for (int q = 0; q < 2; q++) {
                uint32_t badr = (wn * 32 + q * 16) * GBP + boff;
                uint32_t bh[2][2], bl[2][2];
                uint32_t t4[4];
                ldsm_x4(t4, bHb + badr);
                bh[0][0] = t4[0]; bh[0][1] = t4[1];
                bh[1][0] = t4[2]; bh[1][1] = t4[3];
                ldsm_x4(t4, bLb + badr);
                bl[0][0] = t4[0]; bl[0][1] = t4[1];
                bl[1][0] = t4[2]; bl[1][1] = t4[3];
#pragma unroll
                for (int mf = 0; mf < 4; mf++)
#pragma unroll
                    for (int e = 0; e < 2; e++) {
                        int nf = 2 * q + e;
                        mma_fp16(acc[mf][nf], a_h[mf], bh[e]);
                        mma_fp16(acc[mf][nf], a_h[mf], bl[e]);
                    }
            }
        }
        __syncthreads();
    }

    // epilogue: bias + GLU (even B-row = a, odd = g, register-local pair)
#pragma unroll
    for (int nf = 0; nf < 4; nf++) {
        int p = wn * 16 + nf * 4 + (lane & 3);
        int col = N0a + p;
        float ba = bias[col];
        float bg = bias[1024 + col];
#pragma unroll
        for (int mf = 0; mf < 4; mf++) {
            int m = M0 + wm * 64 + mf * 16 + (lane >> 2);
            float a0 = acc[mf][nf][0] + ba;
            float g0 = acc[mf][nf][1] + bg;
            float a1 = acc[mf][nf][2] + ba;
            float g1 = acc[mf][nf][3] + bg;
            out[(size_t)m * 1024 + col]       = a0 / (1.0f + expf(-g0));
            out[(size_t)(m + 8) * 1024 + col] = a1 / (1.0f + expf(-g1));
        }
    }
}

// ---------------------------------------------------------------------------
extern "C" void kernel_launch(void* const* d_in, const int* in_sizes, int n_in,
                              void* d_out, int out_size) {
    const float* x      = (const float*)d_in[0];
    const float* log_dt = (const float*)d_in[1];
    const float* Arl    = (const float*)d_in[2];
    const float* Aim    = (const float*)d_in[3];
    const float* Cr     = (const float*)d_in[4];
    const float* Ci     = (const float*)d_in[5];
    const float* D      = (const float*)d_in[6];
    const float* W      = (const float*)d_in[7];
    const float* bias   = (const float*)d_in[8];
    float* out = (float*)d_out;

    float* kern;
    bf16 *xth, *xtl;
    __half *yh, *whT, *wlT;
    cudaGetSymbolAddress((void**)&kern, g_kern);
    cudaGetSymbolAddress((void**)&xth, g_xth);
    cudaGetSymbolAddress((void**)&xtl, g_xtl);
    cudaGetSymbolAddress((void**)&yh, g_yh);
    cudaGetSymbolAddress((void**)&whT, g_whT);
    cudaGetSymbolAddress((void**)&wlT, g_wlT);

    cudaFuncSetAttribute(k_conv_tc, cudaFuncAttributeMaxDynamicSharedMemorySize,
                         SMEM_CONV);
    cudaFuncSetAttribute(k_gemm_mma, cudaFuncAttributeMaxDynamicSharedMemorySize,
                         SMEM_GEMM);

    k_gen<<<dim3(HH, LL / GCH), 32>>>(log_dt, Arl, Aim, Cr, Ci, kern);
    k_prepW<<<dim3(2048 / 32, 1024 / 32), dim3(32, 8)>>>(W, whT, wlT);
    k_xt<<<dim3(LL / 32, HH / 32, BB), dim3(32, 8)>>>(x, xth, xtl);

    k_conv_tc<<<HH, 256, SMEM_CONV>>>(xth, xtl, kern, D, yh);

    dim3 ggrid(1024 / 64, 16384 / 128);   // (16, 128)
    k_gemm_mma<<<ggrid, 256, SMEM_GEMM>>>(yh, whT, wlT, bias, out);
}

// round 13
// speedup vs baseline: 2.4820x; 1.5079x over previous
#include <cuda_runtime.h>
#include <cuda_bf16.h>
#include <cuda_fp16.h>
#include <math.h>
#include <stdint.h>

#define BB 16
#define LL 1024
#define HH 1024
#define NN 64

// scratch (device globals — no allocation allowed)
__device__ float g_kern[HH * LL];              // kern [h][l]
__device__ __half g_xt[HH * BB * LL];          // x^T fp16 [h][b][l]
__device__ __half g_yh[HH * BB * LL];          // y^T fp16 [h][b*l] (k-major)
__device__ __half g_wT[2048 * 1024];           // W^T fp16 [n][k]

// ---- helpers ----------------------------------------------------------------
__device__ __forceinline__ uint32_t smem_u32(const void* p) {
    uint32_t a;
    asm("{ .reg .u64 t; cvta.to.shared.u64 t, %1; cvt.u32.u64 %0, t; }"
        : "=r"(a) : "l"(p));
    return a;
}
#define CP_ASYNC16(dst, src) \
    asm volatile("cp.async.cg.shared.global [%0], [%1], 16;" :: "r"(dst), "l"(src))
#define CP_COMMIT() asm volatile("cp.async.commit_group;" ::: "memory")
#define CP_WAIT1() asm volatile("cp.async.wait_group 1;" ::: "memory")
#define CP_WAIT0() asm volatile("cp.async.wait_group 0;" ::: "memory")

__device__ __forceinline__ void ldsm_x4(uint32_t* r, uint32_t addr) {
    asm volatile("ldmatrix.sync.aligned.m8n8.x4.shared.b16 {%0,%1,%2,%3}, [%4];"
                 : "=r"(r[0]), "=r"(r[1]), "=r"(r[2]), "=r"(r[3]) : "r"(addr));
}
__device__ __forceinline__ void ldsm_x4t(uint32_t* r, uint32_t addr) {
    asm volatile("ldmatrix.sync.aligned.m8n8.x4.trans.shared.b16 {%0,%1,%2,%3}, [%4];"
                 : "=r"(r[0]), "=r"(r[1]), "=r"(r[2]), "=r"(r[3]) : "r"(addr));
}
__device__ __forceinline__ void mma_fp16(float* c, const uint32_t* a,
                                         const uint32_t* b) {
    asm volatile(
        "mma.sync.aligned.m16n8k16.row.col.f32.f16.f16.f32 "
        "{%0,%1,%2,%3}, {%4,%5,%6,%7}, {%8,%9}, {%0,%1,%2,%3};"
        : "+f"(c[0]), "+f"(c[1]), "+f"(c[2]), "+f"(c[3])
        : "r"(a[0]), "r"(a[1]), "r"(a[2]), "r"(a[3]), "r"(b[0]), "r"(b[1]));
}
__device__ __forceinline__ float gelu_tanh(float t) {
    float c = 0.7978845608028654f * (t + 0.044715f * t * t * t);
    return 0.5f * t * (1.0f + tanhf(c));
}

// ---------------------------------------------------------------------------
// Kernel 1: S4D kernel generation, L-chunked (8 chunks of 128 per h).
// ---------------------------------------------------------------------------
#define GCH 128

__global__ void k_gen(const float* __restrict__ log_dt,
                      const float* __restrict__ Arl,
                      const float* __restrict__ Aim,
                      const float* __restrict__ Cr,
                      const float* __restrict__ Ci,
                      float* __restrict__ kern) {
    int h = blockIdx.x;
    int l0 = blockIdx.y * GCH;
    int lane = threadIdx.x;
    float dt = expf(log_dt[h]);

    float zr[2], zi[2], wr[2], wi[2];
#pragma unroll
    for (int t = 0; t < 2; t++) {
        int n = lane + t * 32;
        float ar = -expf(Arl[h * NN + n]);
        float ai = Aim[h * NN + n];
        float dr = dt * ar, di = dt * ai;
        float er = expf(dr);
        float sn, cs;
        sincosf(di, &sn, &cs);
        float Er = er * cs - 1.0f, Ei = er * sn;
        float inv = 1.0f / (ar * ar + ai * ai);
        float Fr = (Er * ar + Ei * ai) * inv;
        float Fi = (Ei * ar - Er * ai) * inv;
        float cr = Cr[h * NN + n], ci = Ci[h * NN + n];
        float c0r = cr * Fr - ci * Fi;
        float c0i = cr * Fi + ci * Fr;
        float e0 = expf(dr * (float)l0);
        float s0, q0;
        sincosf(di * (float)l0, &s0, &q0);
        float pr = e0 * q0, pi = e0 * s0;
        zr[t] = c0r * pr - c0i * pi;
        zi[t] = c0r * pi + c0i * pr;
        wr[t] = er * cs;
        wi[t] = er * sn;
    }
    float* kout = kern + (size_t)h * LL + l0;
    for (int l = 0; l < GCH; l++) {
        float s = zr[0] + zr[1];
#pragma unroll
        for (int o = 16; o > 0; o >>= 1)
            s += __shfl_xor_sync(0xffffffffu, s, o);
        if (lane == 0) kout[l] = 2.0f * s;
#pragma unroll
        for (int t = 0; t < 2; t++) {
            float tr = zr[t] * wr[t] - zi[t] * wi[t];
            zi[t] = zr[t] * wi[t] + zi[t] * wr[t];
            zr[t] = tr;
        }
    }
}

// ---------------------------------------------------------------------------
// Kernel 1b: W [1024,2048] -> W^T fp16 [2048][1024] (single precision term)
// ---------------------------------------------------------------------------
__global__ void k_prepW(const float* __restrict__ W, __half* __restrict__ wT) {
    __shared__ float t[32][33];
    int tx = threadIdx.x, ty = threadIdx.y;
    int n0 = blockIdx.x * 32, k0 = blockIdx.y * 32;
#pragma unroll
    for (int i = 0; i < 4; i++)
        t[ty + i * 8][tx] = W[(size_t)(k0 + ty + i * 8) * 2048 + n0 + tx];
    __syncthreads();
#pragma unroll
    for (int i = 0; i < 4; i++) {
        int n = n0 + ty + i * 8;
        wT[(size_t)n * 1024 + k0 + tx] = __float2half(t[tx][ty + i * 8]);
    }
}

// ---------------------------------------------------------------------------
// Kernel 1c: x [b][l][h] f32 -> x^T fp16 [h][b][l]
// ---------------------------------------------------------------------------
__global__ void k_xt(const float* __restrict__ x, __half* __restrict__ xt) {
    __shared__ float t[32][33];
    int tx = threadIdx.x, ty = threadIdx.y;
    int l0 = blockIdx.x * 32, h0 = blockIdx.y * 32, b = blockIdx.z;
    const float* xb = x + (size_t)b * LL * HH;
#pragma unroll
    for (int i = 0; i < 4; i++)
        t[ty + i * 8][tx] = xb[(size_t)(l0 + ty + i * 8) * HH + h0 + tx];
    __syncthreads();
#pragma unroll
    for (int i = 0; i < 4; i++) {
        int hh = ty + i * 8;
        size_t o = (size_t)(h0 + hh) * (BB * LL) + (size_t)b * LL + l0 + tx;
        xt[o] = __float2half(t[tx][hh]);
    }
}

// ---------------------------------------------------------------------------
// Kernel 2: Toeplitz tensor-core causal conv + D-skip + gelu, PURE fp16.
// R10 winner structure; single-precision T and x (1 mma term instead of 3).
// A = T_d [lout=64 m], B = x [b=16 n]. 2 CTAs/SM.
// ---------------------------------------------------------------------------
#define XP 2064                       // x smem pitch (1024 fp16 + 8 pad)
#define TP 144                        // T smem pitch (64 fp16 + 8 pad)
#define SM_X 0                        // 16 * XP = 33024
#define SM_K 33024                    // kern f32, 4096
#define SM_T 37120                    // [2 buf][64*144 = 9216]
#define TBUF 9216
#define SM_EP 33024                   // epilogue scratch (reuses ks+T), 8*4352
#define SMEM_CONV 67840

__global__ __launch_bounds__(256, 2) void k_conv_tc(
    const __half* __restrict__ xt,
    const float* __restrict__ kern, const float* __restrict__ D,
    __half* __restrict__ yh) {
    extern __shared__ __align__(128) char smem[];
    uint32_t sb = smem_u32(smem);
    int tid = threadIdx.x;
    int wid = tid >> 5;
    int lane = tid & 31;
    int h = blockIdx.x;

    // async-load x (16 b-rows x 2048 B)
    {
        const __half* s0 = xt + (size_t)h * (BB * LL);
        for (int i = tid; i < 2048; i += 256) {
            int b = i >> 7, g = i & 127;
            CP_ASYNC16(sb + SM_X + b * XP + g * 16, s0 + (size_t)b * LL + g * 8);
        }
    }
    CP_COMMIT();

    float* ks = (float*)(smem + SM_K);
    for (int i = tid; i < 1024; i += 256) ks[i] = kern[(size_t)h * LL + i];
    __syncthreads();

    // build T_0 (buf 0), single fp16
    for (int i = tid; i < 4096; i += 256) {
        int r = i >> 6, c = i & 63;
        int off = r - c;
        float v = (off >= 0) ? ks[off] : 0.0f;
        *(__half*)(smem + SM_T + r * TP + c * 2) = __float2half(v);
    }
    CP_WAIT0();
    __syncthreads();

    float acc[2][4][2][4];
#pragma unroll
    for (int t = 0; t < 2; t++)
#pragma unroll
        for (int mf = 0; mf < 4; mf++)
#pragma unroll
            for (int nf = 0; nf < 2; nf++)
#pragma unroll
                for (int e = 0; e < 4; e++) acc[t][mf][nf][e] = 0.0f;

#pragma unroll 1
    for (int d = 0; d < 16; d++) {
        int bufT = d & 1;
        if (d > 0) {
            __syncthreads();
            for (int i = tid; i < 4096; i += 256) {
                int r = i >> 6, c = i & 63;
                float v = ks[d * 64 + r - c];
                *(__half*)(smem + SM_T + bufT * TBUF + r * TP + c * 2) =
                    __float2half(v);
            }
            __syncthreads();
        }
        uint32_t tH = sb + SM_T + bufT * TBUF;
#pragma unroll
        for (int t = 0; t < 2; t++) {
            int li = t ? (15 - wid) : wid;
            if (li < d) continue;
            int ji = li - d;
#pragma unroll
            for (int kc = 0; kc < 4; kc++) {
                uint32_t a_h[4][4];
                uint32_t arow = (lane & 15) * TP + kc * 32 + (lane >> 4) * 16;
#pragma unroll
                for (int mf = 0; mf < 4; mf++)
                    ldsm_x4(a_h[mf], tH + mf * 16 * TP + arow);
                uint32_t bh[2][2];
                uint32_t boff = (((lane >> 4) & 1) * 8 + (lane & 7)) * XP +
                                ji * 128 + kc * 32 + ((lane >> 3) & 1) * 16;
                {
                    uint32_t t4[4];
                    ldsm_x4(t4, sb + SM_X + boff);
                    bh[0][0] = t4[0]; bh[0][1] = t4[1];
                    bh[1][0] = t4[2]; bh[1][1] = t4[3];
                }
#pragma unroll
                for (int mf = 0; mf < 4; mf++)
#pragma unroll
                    for (int nf = 0; nf < 2; nf++)
                        mma_fp16(acc[t][mf][nf], a_h[mf], bh[nf]);
            }
        }
    }

    __syncthreads();
    float Dh = D[h];
    float* epf = (float*)(smem + SM_EP + wid * 4352);
#pragma unroll 1
    for (int t = 0; t < 2; t++) {
        int li = t ? (15 - wid) : wid;
        int r0 = lane >> 2, cc = (lane & 3) * 2;
#pragma unroll
        for (int mf = 0; mf < 4; mf++)
#pragma unroll
            for (int nf = 0; nf < 2; nf++) {
                int bq = nf * 8 + cc;
                int lq = mf * 16 + r0;
                epf[bq * 68 + lq]           = acc[t][mf][nf][0];
                epf[(bq + 1) * 68 + lq]     = acc[t][mf][nf][1];
                epf[bq * 68 + lq + 8]       = acc[t][mf][nf][2];
                epf[(bq + 1) * 68 + lq + 8] = acc[t][mf][nf][3];
            }
        __syncwarp();
#pragma unroll
        for (int i = lane; i < 1024; i += 32) {
            int b = i >> 6, l = i & 63;
            int lout = li * 64 + l;
            float xv = __half2float(*(__half*)(smem + SM_X + b * XP + lout * 2));
            float v = gelu_tanh(epf[b * 68 + l] + xv * Dh);
            size_t o = (size_t)h * (BB * LL) + (size_t)b * LL + lout;
            yh[o] = __float2half(v);
        }
        __syncwarp();
    }
}

// ---------------------------------------------------------------------------
// Kernel 3: mma.sync fp16 1-term GEMM + bias + GLU. z = Yh*W.
// 2 CTAs/SM, 2-stage pipe. CTA 128m x 128 B-rows (64 out cols, a/g
// interleaved); warp 64m x 32 B-rows.
// ---------------------------------------------------------------------------
#define GAP 272                         // A smem pitch (128 m fp16 + 8 pad)
#define GABUF (32 * GAP)                // 8704
#define GBP 80                          // B smem pitch (32 k fp16 + 8 pad)
#define GBBUF (128 * GBP)               // 10240
#define SM_GA 0                         // [2 buf][GABUF] = 17408
#define SM_GB 17408                     // [2 buf][GBBUF] = 20480
#define SMEM_GEMM 37888
#define GNS 32                          // K stages (1024/32)

__global__ __launch_bounds__(256, 2) void k_gemm_mma(
    const __half* __restrict__ Yh, const __half* __restrict__ WT,
    const float* __restrict__ bias, float* __restrict__ out) {
    extern __shared__ __align__(128) char smem[];
    uint32_t sb = smem_u32(smem);
    int tid = threadIdx.x;
    int wid = tid >> 5;
    int lane = tid & 31;
    int wm = wid >> 2;                  // 0/1 -> m half (64 each)
    int wn = wid & 3;                   // 0..3 -> 32 B-rows each
    int N0a = blockIdx.x * 64;          // 64 output cols per CTA
    int M0 = blockIdx.y * 128;

    float acc[4][4][4];
#pragma unroll
    for (int i = 0; i < 4; i++)
#pragma unroll
        for (int j = 0; j < 4; j++)
#pragma unroll
            for (int e = 0; e < 4; e++) acc[i][j][e] = 0.0f;

#define G_ISSUE(S)                                                              \
    {                                                                           \
        int _s = (S);                                                           \
        int _buf = _s & 1;                                                      \
        int K0 = _s * 32;                                                       \
        _Pragma("unroll") for (int it = 0; it < 4; it++) {                      \
            int i = tid + it * 256;                                             \
            const __half* src;                                                  \
            uint32_t dst;                                                       \
            if (i < 512) {                                                      \
                int r = i >> 4, g = i & 15;                                     \
                src = Yh + (size_t)(K0 + r) * 16384 + M0 + g * 8;               \
                dst = sb + SM_GA + _buf * GABUF + r * GAP + g * 16;             \
            } else {                                                            \
                int j = i - 512;                                                \
                int rr = j >> 2, g = j & 3;                                     \
                int n = (rr & 1) ? (1024 + N0a + (rr >> 1)) : (N0a + (rr >> 1));\
                src = WT + (size_t)n * 1024 + K0 + g * 8;                       \
                dst = sb + SM_GB + _buf * GBBUF + rr * GBP + g * 16;            \
            }                                                                   \
            CP_ASYNC16(dst, src);                                               \
        }                                                                       \
        CP_COMMIT();                                                            \
    }

    G_ISSUE(0);
#pragma unroll 1
    for (int s = 0; s < GNS; s++) {
        int buf = s & 1;
        if (s + 1 < GNS) {
            G_ISSUE(s + 1);
            CP_WAIT1();
        } else {
            CP_WAIT0();
        }
        __syncthreads();

        uint32_t aHb = sb + SM_GA + buf * GABUF;
        uint32_t bHb = sb + SM_GB + buf * GBBUF;

#pragma unroll
        for (int kc = 0; kc < 2; kc++) {
            uint32_t a_h[4][4];
            uint32_t arow = (kc * 16 + ((lane >> 4) & 1) * 8 + (lane & 7)) * GAP;
#pragma unroll
            for (int mf = 0; mf < 4; mf++) {
                uint32_t ao = arow + (wm * 64 + mf * 16 + ((lane >> 3) & 1) * 8) * 2;
                ldsm_x4t(a_h[mf], aHb + ao);
            }
            uint32_t boff = (((lane >> 4) & 1) * 8 + (lane & 7)) * GBP +
                            kc * 32 + ((lane >> 3) & 1) * 16;
#pragma unroll
            for (int q = 0; q < 2; q++) {
                uint32_t badr = (wn * 32 + q * 16) * GBP + boff;
                uint32_t bh[2][2];
                uint32_t t4[4];
                ldsm_x4(t4, bHb + badr);
                bh[0][0] = t4[0]; bh[0][1] = t4[1];
                bh[1][0] = t4[2]; bh[1][1] = t4[3];
#pragma unroll
                for (int mf = 0; mf < 4; mf++)
#pragma unroll
                    for (int e = 0; e < 2; e++)
                        mma_fp16(acc[mf][2 * q + e], a_h[mf], bh[e]);
            }
        }
        __syncthreads();
    }

    // epilogue: bias + GLU (even B-row = a, odd = g, register-local pair)
#pragma unroll
    for (int nf = 0; nf < 4; nf++) {
        int p = wn * 16 + nf * 4 + (lane & 3);
        int col = N0a + p;
        float ba = bias[col];
        float bg = bias[1024 + col];
#pragma unroll
        for (int mf = 0; mf < 4; mf++) {
            int m = M0 + wm * 64 + mf * 16 + (lane >> 2);
            float a0 = acc[mf][nf][0] + ba;
            float g0 = acc[mf][nf][1] + bg;
            float a1 = acc[mf][nf][2] + ba;
            float g1 = acc[mf][nf][3] + bg;
            out[(size_t)m * 1024 + col]       = a0 / (1.0f + expf(-g0));
            out[(size_t)(m + 8) * 1024 + col] = a1 / (1.0f + expf(-g1));
        }
    }
}

// ---------------------------------------------------------------------------
extern "C" void kernel_launch(void* const* d_in, const int* in_sizes, int n_in,
                              void* d_out, int out_size) {
    const float* x      = (const float*)d_in[0];
    const float* log_dt = (const float*)d_in[1];
    const float* Arl    = (const float*)d_in[2];
    const float* Aim    = (const float*)d_in[3];
    const float* Cr     = (const float*)d_in[4];
    const float* Ci     = (const float*)d_in[5];
    const float* D      = (const float*)d_in[6];
    const float* W      = (const float*)d_in[7];
    const float* bias   = (const float*)d_in[8];
    float* out = (float*)d_out;

    float* kern;
    __half *xt, *yh, *wT;
    cudaGetSymbolAddress((void**)&kern, g_kern);
    cudaGetSymbolAddress((void**)&xt, g_xt);
    cudaGetSymbolAddress((void**)&yh, g_yh);
    cudaGetSymbolAddress((void**)&wT, g_wT);

    cudaFuncSetAttribute(k_conv_tc, cudaFuncAttributeMaxDynamicSharedMemorySize,
                         SMEM_CONV);
    cudaFuncSetAttribute(k_gemm_mma, cudaFuncAttributeMaxDynamicSharedMemorySize,
                         SMEM_GEMM);

    k_gen<<<dim3(HH, LL / GCH), 32>>>(log_dt, Arl, Aim, Cr, Ci, kern);
    k_prepW<<<dim3(2048 / 32, 1024 / 32), dim3(32, 8)>>>(W, wT);
    k_xt<<<dim3(LL / 32, HH / 32, BB), dim3(32, 8)>>>(x, xt);

    k_conv_tc<<<HH, 256, SMEM_CONV>>>(xt, kern, D, yh);

    dim3 ggrid(1024 / 64, 16384 / 128);   // (16, 128)
    k_gemm_mma<<<ggrid, 256, SMEM_GEMM>>>(yh, wT, bias, out);
}

// round 14
// speedup vs baseline: 2.8605x; 1.1525x over previous
#include <cuda_runtime.h>
#include <cuda_bf16.h>
#include <cuda_fp16.h>
#include <math.h>
#include <stdint.h>

#define BB 16
#define LL 1024
#define HH 1024
#define NN 64

// scratch (device globals — no allocation allowed)
__device__ float g_kern[HH * LL];              // kern [h][l]
__device__ __half g_xt[HH * BB * LL];          // x^T fp16 [h][b][l]
__device__ __half g_yh[HH * BB * LL];          // y^T fp16 [h][b*l] (k-major)
__device__ __half g_wT[2048 * 1024];           // W^T fp16 [n][k]

// ---- helpers ----------------------------------------------------------------
__device__ __forceinline__ uint32_t smem_u32(const void* p) {
    uint32_t a;
    asm("{ .reg .u64 t; cvta.to.shared.u64 t, %1; cvt.u32.u64 %0, t; }"
        : "=r"(a) : "l"(p));
    return a;
}
#define CP_ASYNC16(dst, src) \
    asm volatile("cp.async.cg.shared.global [%0], [%1], 16;" :: "r"(dst), "l"(src))
#define CP_COMMIT() asm volatile("cp.async.commit_group;" ::: "memory")
#define CP_WAIT1() asm volatile("cp.async.wait_group 1;" ::: "memory")
#define CP_WAIT0() asm volatile("cp.async.wait_group 0;" ::: "memory")

__device__ __forceinline__ void ldsm_x4(uint32_t* r, uint32_t addr) {
    asm volatile("ldmatrix.sync.aligned.m8n8.x4.shared.b16 {%0,%1,%2,%3}, [%4];"
                 : "=r"(r[0]), "=r"(r[1]), "=r"(r[2]), "=r"(r[3]) : "r"(addr));
}
__device__ __forceinline__ void ldsm_x4t(uint32_t* r, uint32_t addr) {
    asm volatile("ldmatrix.sync.aligned.m8n8.x4.trans.shared.b16 {%0,%1,%2,%3}, [%4];"
                 : "=r"(r[0]), "=r"(r[1]), "=r"(r[2]), "=r"(r[3]) : "r"(addr));
}
__device__ __forceinline__ void mma_fp16(float* c, const uint32_t* a,
                                         const uint32_t* b) {
    asm volatile(
        "mma.sync.aligned.m16n8k16.row.col.f32.f16.f16.f32 "
        "{%0,%1,%2,%3}, {%4,%5,%6,%7}, {%8,%9}, {%0,%1,%2,%3};"
        : "+f"(c[0]), "+f"(c[1]), "+f"(c[2]), "+f"(c[3])
        : "r"(a[0]), "r"(a[1]), "r"(a[2]), "r"(a[3]), "r"(b[0]), "r"(b[1]));
}
__device__ __forceinline__ float gelu_tanh(float t) {
    float c = 0.7978845608028654f * (t + 0.044715f * t * t * t);
    return 0.5f * t * (1.0f + tanhf(c));
}

// ---------------------------------------------------------------------------
// Kernel 1: S4D kernel generation, L-chunked (8 chunks of 128 per h).
// ---------------------------------------------------------------------------
#define GCH 128

__global__ void k_gen(const float* __restrict__ log_dt,
                      const float* __restrict__ Arl,
                      const float* __restrict__ Aim,
                      const float* __restrict__ Cr,
                      const float* __restrict__ Ci,
                      float* __restrict__ kern) {
    int h = blockIdx.x;
    int l0 = blockIdx.y * GCH;
    int lane = threadIdx.x;
    float dt = expf(log_dt[h]);

    float zr[2], zi[2], wr[2], wi[2];
#pragma unroll
    for (int t = 0; t < 2; t++) {
        int n = lane + t * 32;
        float ar = -expf(Arl[h * NN + n]);
        float ai = Aim[h * NN + n];
        float dr = dt * ar, di = dt * ai;
        float er = expf(dr);
        float sn, cs;
        sincosf(di, &sn, &cs);
        float Er = er * cs - 1.0f, Ei = er * sn;
        float inv = 1.0f / (ar * ar + ai * ai);
        float Fr = (Er * ar + Ei * ai) * inv;
        float Fi = (Ei * ar - Er * ai) * inv;
        float cr = Cr[h * NN + n], ci = Ci[h * NN + n];
        float c0r = cr * Fr - ci * Fi;
        float c0i = cr * Fi + ci * Fr;
        float e0 = expf(dr * (float)l0);
        float s0, q0;
        sincosf(di * (float)l0, &s0, &q0);
        float pr = e0 * q0, pi = e0 * s0;
        zr[t] = c0r * pr - c0i * pi;
        zi[t] = c0r * pi + c0i * pr;
        wr[t] = er * cs;
        wi[t] = er * sn;
    }
    float* kout = kern + (size_t)h * LL + l0;
    for (int l = 0; l < GCH; l++) {
        float s = zr[0] + zr[1];
#pragma unroll
        for (int o = 16; o > 0; o >>= 1)
            s += __shfl_xor_sync(0xffffffffu, s, o);
        if (lane == 0) kout[l] = 2.0f * s;
#pragma unroll
        for (int t = 0; t < 2; t++) {
            float tr = zr[t] * wr[t] - zi[t] * wi[t];
            zi[t] = zr[t] * wi[t] + zi[t] * wr[t];
            zr[t] = tr;
        }
    }
}

// ---------------------------------------------------------------------------
// Kernel 1b: W [1024,2048] -> W^T fp16 [2048][1024]
// ---------------------------------------------------------------------------
__global__ void k_prepW(const float* __restrict__ W, __half* __restrict__ wT) {
    __shared__ float t[32][33];
    int tx = threadIdx.x, ty = threadIdx.y;
    int n0 = blockIdx.x * 32, k0 = blockIdx.y * 32;
#pragma unroll
    for (int i = 0; i < 4; i++)
        t[ty + i * 8][tx] = W[(size_t)(k0 + ty + i * 8) * 2048 + n0 + tx];
    __syncthreads();
#pragma unroll
    for (int i = 0; i < 4; i++) {
        int n = n0 + ty + i * 8;
        wT[(size_t)n * 1024 + k0 + tx] = __float2half(t[tx][ty + i * 8]);
    }
}

// ---------------------------------------------------------------------------
// Kernel 1c: x [b][l][h] f32 -> x^T fp16 [h][b][l]
// ---------------------------------------------------------------------------
__global__ void k_xt(const float* __restrict__ x, __half* __restrict__ xt) {
    __shared__ float t[32][33];
    int tx = threadIdx.x, ty = threadIdx.y;
    int l0 = blockIdx.x * 32, h0 = blockIdx.y * 32, b = blockIdx.z;
    const float* xb = x + (size_t)b * LL * HH;
#pragma unroll
    for (int i = 0; i < 4; i++)
        t[ty + i * 8][tx] = xb[(size_t)(l0 + ty + i * 8) * HH + h0 + tx];
    __syncthreads();
#pragma unroll
    for (int i = 0; i < 4; i++) {
        int hh = ty + i * 8;
        size_t o = (size_t)(h0 + hh) * (BB * LL) + (size_t)b * LL + l0 + tx;
        xt[o] = __float2half(t[tx][hh]);
    }
}

// ---------------------------------------------------------------------------
// Kernel 2: Toeplitz tensor-core causal conv, NO T materialization.
// A fragment of T_d is (kern[u], kern[u-1]) at u = 16+64d+m-k_even, so all
// fragments for a (warp, d) come from 15 shared LDS.32 of a packed pair
// array khd[u] = (fp16 k[u-16] | fp16 k[u-17] << 16). No syncs in main loop.
// ---------------------------------------------------------------------------
#define XP 2064                       // x smem pitch (1024 fp16 + 8 pad)
#define SM_X 0                        // 16 * XP = 33024
#define SM_KS 33024                   // kern f32 [33024, 37120)
#define SM_KHD 37120                  // khd u32 [1104] -> [37120, 41536)
#define SM_EP 41536                   // 8 warps * 4352
#define SMEM_CONV 76352

__global__ __launch_bounds__(256, 2) void k_conv_tc(
    const __half* __restrict__ xt,
    const float* __restrict__ kern, const float* __restrict__ D,
    __half* __restrict__ yh) {
    extern __shared__ __align__(128) char smem[];
    uint32_t sb = smem_u32(smem);
    int tid = threadIdx.x;
    int wid = tid >> 5;
    int lane = tid & 31;
    int h = blockIdx.x;

    // async-load x (16 b-rows x 2048 B)
    {
        const __half* s0 = xt + (size_t)h * (BB * LL);
        for (int i = tid; i < 2048; i += 256) {
            int b = i >> 7, g = i & 127;
            CP_ASYNC16(sb + SM_X + b * XP + g * 16, s0 + (size_t)b * LL + g * 8);
        }
    }
    CP_COMMIT();

    float* ks = (float*)(smem + SM_KS);
    for (int i = tid; i < 1024; i += 256) ks[i] = kern[(size_t)h * LL + i];
    __syncthreads();

    // build khd once: array index i = logical u + 64; khp[j] = kern[j-16]
    uint32_t* khd = (uint32_t*)(smem + SM_KHD);
    for (int i = tid; i < 1104; i += 256) {
        int u = i - 64;
        int j0 = u - 16, j1 = u - 17;
        float lo = (j0 >= 0 && j0 < 1024) ? ks[j0] : 0.0f;
        float hi = (j1 >= 0 && j1 < 1024) ? ks[j1] : 0.0f;
        __half2 p = __floats2half2_rn(lo, hi);
        khd[i] = *(uint32_t*)&p;
    }
    CP_WAIT0();
    __syncthreads();

    float acc[2][4][2][4];
#pragma unroll
    for (int t = 0; t < 2; t++)
#pragma unroll
        for (int mf = 0; mf < 4; mf++)
#pragma unroll
            for (int nf = 0; nf < 2; nf++)
#pragma unroll
                for (int e = 0; e < 4; e++) acc[t][mf][nf][e] = 0.0f;

    int li0 = wid;
    int li1 = 15 - wid;
    int lanebase = (lane >> 2) - 2 * (lane & 3);

#pragma unroll 1
    for (int d = 0; d <= li1; d++) {
        // 15 shared A-source words for this (warp, d)
        uint32_t kv[15];
        int b0 = 64 + 16 + 64 * d + lanebase;   // khd array index, t=0 center
#pragma unroll
        for (int j = 0; j < 15; j++) kv[j] = khd[b0 + 8 * (j - 7)];
#pragma unroll
        for (int t = 0; t < 2; t++) {
            int li = t ? li1 : li0;
            if (li < d) continue;
            int ji = li - d;
#pragma unroll
            for (int kc = 0; kc < 4; kc++) {
                uint32_t bh[2][2];
                uint32_t boff = (((lane >> 4) & 1) * 8 + (lane & 7)) * XP +
                                ji * 128 + kc * 32 + ((lane >> 3) & 1) * 16;
                {
                    uint32_t t4[4];
                    ldsm_x4(t4, sb + SM_X + boff);
                    bh[0][0] = t4[0]; bh[0][1] = t4[1];
                    bh[1][0] = t4[2]; bh[1][1] = t4[3];
                }
#pragma unroll
                for (int mf = 0; mf < 4; mf++) {
                    int idx = 7 + 2 * (mf - kc);
                    uint32_t a[4] = {kv[idx], kv[idx + 1], kv[idx - 1], kv[idx]};
                    mma_fp16(acc[t][mf][0], a, bh[0]);
                    mma_fp16(acc[t][mf][1], a, bh[1]);
                }
            }
        }
    }

    float Dh = D[h];
    float* epf = (float*)(smem + SM_EP + wid * 4352);   // per-warp exclusive
#pragma unroll 1
    for (int t = 0; t < 2; t++) {
        int li = t ? li1 : li0;
        int r0 = lane >> 2, cc = (lane & 3) * 2;
#pragma unroll
        for (int mf = 0; mf < 4; mf++)
#pragma unroll
            for (int nf = 0; nf < 2; nf++) {
                int bq = nf * 8 + cc;
                int lq = mf * 16 + r0;
                epf[bq * 68 + lq]           = acc[t][mf][nf][0];
                epf[(bq + 1) * 68 + lq]     = acc[t][mf][nf][1];
                epf[bq * 68 + lq + 8]       = acc[t][mf][nf][2];
                epf[(bq + 1) * 68 + lq + 8] = acc[t][mf][nf][3];
            }
        __syncwarp();
#pragma unroll
        for (int i = lane; i < 1024; i += 32) {
            int b = i >> 6, l = i & 63;
            int lout = li * 64 + l;
            float xv = __half2float(*(__half*)(smem + SM_X + b * XP + lout * 2));
            float v = gelu_tanh(epf[b * 68 + l] + xv * Dh);
            size_t o = (size_t)h * (BB * LL) + (size_t)b * LL + lout;
            yh[o] = __float2half(v);
        }
        __syncwarp();
    }
}

// ---------------------------------------------------------------------------
// Kernel 3: mma.sync fp16 1-term GEMM + bias + GLU. K-stage 64 (16 stages,
// half the barriers of R13). 2 CTAs/SM, 2-stage pipe. CTA 128m x 128 B-rows.
// ---------------------------------------------------------------------------
#define GAP 272                         // A smem pitch (128 m fp16 + 8 pad)
#define GABUF (64 * GAP)                // 17408
#define GBP 144                         // B smem pitch (64 k fp16 + 8 pad)
#define GBBUF (128 * GBP)               // 18432
#define SM_GA 0                         // [2 buf][GABUF] = 34816
#define SM_GB 34816                     // [2 buf][GBBUF] = 36864
#define SMEM_GEMM 71680
#define GNS 16                          // K stages (1024/64)

__global__ __launch_bounds__(256, 2) void k_gemm_mma(
    const __half* __restrict__ Yh, const __half* __restrict__ WT,
    const float* __restrict__ bias, float* __restrict__ out) {
    extern __shared__ __align__(128) char smem[];
    uint32_t sb = smem_u32(smem);
    int tid = threadIdx.x;
    int wid = tid >> 5;
    int lane = tid & 31;
    int wm = wid >> 2;                  // 0/1 -> m half (64 each)
    int wn = wid & 3;                   // 0..3 -> 32 B-rows each
    int N0a = blockIdx.x * 64;          // 64 output cols per CTA
    int M0 = blockIdx.y * 128;

    float acc[4][4][4];
#pragma unroll
    for (int i = 0; i < 4; i++)
#pragma unroll
        for (int j = 0; j < 4; j++)
#pragma unroll
            for (int e = 0; e < 4; e++) acc[i][j][e] = 0.0f;

#define G_ISSUE(S)                                                              \
    {                                                                           \
        int _s = (S);                                                           \
        int _buf = _s & 1;                                                      \
        int K0 = _s * 64;                                                       \
        _Pragma("unroll") for (int it = 0; it < 8; it++) {                      \
            int i = tid + it * 256;                                             \
            const __half* src;                                                  \
            uint32_t dst;                                                       \
            if (i < 1024) {                                                     \
                int r = i >> 4, g = i & 15;                                     \
                src = Yh + (size_t)(K0 + r) * 16384 + M0 + g * 8;               \
                dst = sb + SM_GA + _buf * GABUF + r * GAP + g * 16;             \
            } else {                                                            \
                int j = i - 1024;                                               \
                int rr = j >> 3, g = j & 7;                                     \
                int n = (rr & 1) ? (1024 + N0a + (rr >> 1)) : (N0a + (rr >> 1));\
                src = WT + (size_t)n * 1024 + K0 + g * 8;                       \
                dst = sb + SM_GB + _buf * GBBUF + rr * GBP + g * 16;            \
            }                                                                   \
            CP_ASYNC16(dst, src);                                               \
        }                                                                       \
        CP_COMMIT();                                                            \
    }

    G_ISSUE(0);
#pragma unroll 1
    for (int s = 0; s < GNS; s++) {
        int buf = s & 1;
        if (s + 1 < GNS) {
            G_ISSUE(s + 1);
            CP_WAIT1();
        } else {
            CP_WAIT0();
        }
        __syncthreads();

        uint32_t aHb = sb + SM_GA + buf * GABUF;
        uint32_t bHb = sb + SM_GB + buf * GBBUF;

#pragma unroll
        for (int kc = 0; kc < 4; kc++) {
            uint32_t a_h[4][4];
            uint32_t arow = (kc * 16 + ((lane >> 4) & 1) * 8 + (lane & 7)) * GAP;
#pragma unroll
            for (int mf = 0; mf < 4; mf++) {
                uint32_t ao = arow + (wm * 64 + mf * 16 + ((lane >> 3) & 1) * 8) * 2;
                ldsm_x4t(a_h[mf], aHb + ao);
            }
            uint32_t boff = (((lane >> 4) & 1) * 8 + (lane & 7)) * GBP +
                            kc * 32 + ((lane >> 3) & 1) * 16;
#pragma unroll
            for (int q = 0; q < 2; q++) {
                uint32_t badr = (wn * 32 + q * 16) * GBP + boff;
                uint32_t bh[2][2];
                uint32_t t4[4];
                ldsm_x4(t4, bHb + badr);
                bh[0][0] = t4[0]; bh[0][1] = t4[1];
                bh[1][0] = t4[2]; bh[1][1] = t4[3];
#pragma unroll
                for (int mf = 0; mf < 4; mf++)
#pragma unroll
                    for (int e = 0; e < 2; e++)
                        mma_fp16(acc[mf][2 * q + e], a_h[mf], bh[e]);
            }
        }
        __syncthreads();
    }

    // epilogue: bias + GLU (even B-row = a, odd = g, register-local pair)
#pragma unroll
    for (int nf = 0; nf < 4; nf++) {
        int p = wn * 16 + nf * 4 + (lane & 3);
        int col = N0a + p;
        float ba = bias[col];
        float bg = bias[1024 + col];
#pragma unroll
        for (int mf = 0; mf < 4; mf++) {
            int m = M0 + wm * 64 + mf * 16 + (lane >> 2);
            float a0 = acc[mf][nf][0] + ba;
            float g0 = acc[mf][nf][1] + bg;
            float a1 = acc[mf][nf][2] + ba;
            float g1 = acc[mf][nf][3] + bg;
            out[(size_t)m * 1024 + col]       = a0 / (1.0f + expf(-g0));
            out[(size_t)(m + 8) * 1024 + col] = a1 / (1.0f + expf(-g1));
        }
    }
}

// ---------------------------------------------------------------------------
extern "C" void kernel_launch(void* const* d_in, const int* in_sizes, int n_in,
                              void* d_out, int out_size) {
    const float* x      = (const float*)d_in[0];
    const float* log_dt = (const float*)d_in[1];
    const float* Arl    = (const float*)d_in[2];
    const float* Aim    = (const float*)d_in[3];
    const float* Cr     = (const float*)d_in[4];
    const float* Ci     = (const float*)d_in[5];
    const float* D      = (const float*)d_in[6];
    const float* W      = (const float*)d_in[7];
    const float* bias   = (const float*)d_in[8];
    float* out = (float*)d_out;

    float* kern;
    __half *xt, *yh, *wT;
    cudaGetSymbolAddress((void**)&kern, g_kern);
    cudaGetSymbolAddress((void**)&xt, g_xt);
    cudaGetSymbolAddress((void**)&yh, g_yh);
    cudaGetSymbolAddress((void**)&wT, g_wT);

    cudaFuncSetAttribute(k_conv_tc, cudaFuncAttributeMaxDynamicSharedMemorySize,
                         SMEM_CONV);
    cudaFuncSetAttribute(k_gemm_mma, cudaFuncAttributeMaxDynamicSharedMemorySize,
                         SMEM_GEMM);

    k_gen<<<dim3(HH, LL / GCH), 32>>>(log_dt, Arl, Aim, Cr, Ci, kern);
    k_prepW<<<dim3(2048 / 32, 1024 / 32), dim3(32, 8)>>>(W, wT);
    k_xt<<<dim3(LL / 32, HH / 32, BB), dim3(32, 8)>>>(x, xt);

    k_conv_tc<<<HH, 256, SMEM_CONV>>>(xt, kern, D, yh);

    dim3 ggrid(1024 / 64, 16384 / 128);   // (16, 128)
    k_gemm_mma<<<ggrid, 256, SMEM_GEMM>>>(yh, wT, bias, out);
}

// round 15
// speedup vs baseline: 2.8761x; 1.0054x over previous
#include <cuda_runtime.h>
#include <cuda_bf16.h>
#include <cuda_fp16.h>
#include <math.h>
#include <stdint.h>

#define BB 16
#define LL 1024
#define HH 1024
#define NN 64

// scratch (device globals — no allocation allowed)
__device__ float g_kern[HH * LL];              // kern [h][l]
__device__ __half g_xt[HH * BB * LL];          // x^T fp16 [h][b][l]
__device__ __half g_yh[HH * BB * LL];          // y^T fp16 [h][b*l] (k-major)
__device__ __half g_wT[2048 * 1024];           // W^T fp16 [n][k]

// ---- helpers ----------------------------------------------------------------
__device__ __forceinline__ uint32_t smem_u32(const void* p) {
    uint32_t a;
    asm("{ .reg .u64 t; cvta.to.shared.u64 t, %1; cvt.u32.u64 %0, t; }"
        : "=r"(a) : "l"(p));
    return a;
}
#define CP_ASYNC16(dst, src) \
    asm volatile("cp.async.cg.shared.global [%0], [%1], 16;" :: "r"(dst), "l"(src))
#define CP_COMMIT() asm volatile("cp.async.commit_group;" ::: "memory")
#define CP_WAIT1() asm volatile("cp.async.wait_group 1;" ::: "memory")
#define CP_WAIT0() asm volatile("cp.async.wait_group 0;" ::: "memory")

__device__ __forceinline__ void ldsm_x4(uint32_t* r, uint32_t addr) {
    asm volatile("ldmatrix.sync.aligned.m8n8.x4.shared.b16 {%0,%1,%2,%3}, [%4];"
                 : "=r"(r[0]), "=r"(r[1]), "=r"(r[2]), "=r"(r[3]) : "r"(addr));
}
__device__ __forceinline__ void ldsm_x4t(uint32_t* r, uint32_t addr) {
    asm volatile("ldmatrix.sync.aligned.m8n8.x4.trans.shared.b16 {%0,%1,%2,%3}, [%4];"
                 : "=r"(r[0]), "=r"(r[1]), "=r"(r[2]), "=r"(r[3]) : "r"(addr));
}
__device__ __forceinline__ void mma_fp16(float* c, const uint32_t* a,
                                         const uint32_t* b) {
    asm volatile(
        "mma.sync.aligned.m16n8k16.row.col.f32.f16.f16.f32 "
        "{%0,%1,%2,%3}, {%4,%5,%6,%7}, {%8,%9}, {%0,%1,%2,%3};"
        : "+f"(c[0]), "+f"(c[1]), "+f"(c[2]), "+f"(c[3])
        : "r"(a[0]), "r"(a[1]), "r"(a[2]), "r"(a[3]), "r"(b[0]), "r"(b[1]));
}
__device__ __forceinline__ float gelu_tanh(float t) {
    float c = 0.7978845608028654f * (t + 0.044715f * t * t * t);
    return 0.5f * t * (1.0f + tanhf(c));
}

// ---------------------------------------------------------------------------
// Kernel 1: S4D kernel generation, L-chunked (8 chunks of 128 per h).
// ---------------------------------------------------------------------------
#define GCH 128

__global__ void k_gen(const float* __restrict__ log_dt,
                      const float* __restrict__ Arl,
                      const float* __restrict__ Aim,
                      const float* __restrict__ Cr,
                      const float* __restrict__ Ci,
                      float* __restrict__ kern) {
    int h = blockIdx.x;
    int l0 = blockIdx.y * GCH;
    int lane = threadIdx.x;
    float dt = expf(log_dt[h]);

    float zr[2], zi[2], wr[2], wi[2];
#pragma unroll
    for (int t = 0; t < 2; t++) {
        int n = lane + t * 32;
        float ar = -expf(Arl[h * NN + n]);
        float ai = Aim[h * NN + n];
        float dr = dt * ar, di = dt * ai;
        float er = expf(dr);
        float sn, cs;
        sincosf(di, &sn, &cs);
        float Er = er * cs - 1.0f, Ei = er * sn;
        float inv = 1.0f / (ar * ar + ai * ai);
        float Fr = (Er * ar + Ei * ai) * inv;
        float Fi = (Ei * ar - Er * ai) * inv;
        float cr = Cr[h * NN + n], ci = Ci[h * NN + n];
        float c0r = cr * Fr - ci * Fi;
        float c0i = cr * Fi + ci * Fr;
        float e0 = expf(dr * (float)l0);
        float s0, q0;
        sincosf(di * (float)l0, &s0, &q0);
        float pr = e0 * q0, pi = e0 * s0;
        zr[t] = c0r * pr - c0i * pi;
        zi[t] = c0r * pi + c0i * pr;
        wr[t] = er * cs;
        wi[t] = er * sn;
    }
    float* kout = kern + (size_t)h * LL + l0;
    for (int l = 0; l < GCH; l++) {
        float s = zr[0] + zr[1];
#pragma unroll
        for (int o = 16; o > 0; o >>= 1)
            s += __shfl_xor_sync(0xffffffffu, s, o);
        if (lane == 0) kout[l] = 2.0f * s;
#pragma unroll
        for (int t = 0; t < 2; t++) {
            float tr = zr[t] * wr[t] - zi[t] * wi[t];
            zi[t] = zr[t] * wi[t] + zi[t] * wr[t];
            zr[t] = tr;
        }
    }
}

// ---------------------------------------------------------------------------
// Kernel 1b: W [1024,2048] -> W^T fp16 [2048][1024]
// ---------------------------------------------------------------------------
__global__ void k_prepW(const float* __restrict__ W, __half* __restrict__ wT) {
    __shared__ float t[32][33];
    int tx = threadIdx.x, ty = threadIdx.y;
    int n0 = blockIdx.x * 32, k0 = blockIdx.y * 32;
#pragma unroll
    for (int i = 0; i < 4; i++)
        t[ty + i * 8][tx] = W[(size_t)(k0 + ty + i * 8) * 2048 + n0 + tx];
    __syncthreads();
#pragma unroll
    for (int i = 0; i < 4; i++) {
        int n = n0 + ty + i * 8;
        wT[(size_t)n * 1024 + k0 + tx] = __float2half(t[tx][ty + i * 8]);
    }
}

// ---------------------------------------------------------------------------
// Kernel 1c: x [b][l][h] f32 -> x^T fp16 [h][b][l]. 64l x 32h tiles,
// __half2 stores (full 128B store wavefronts).
// ---------------------------------------------------------------------------
__global__ void k_xt(const float* __restrict__ x, __half* __restrict__ xt) {
    __shared__ float t[64][33];
    int tx = threadIdx.x, ty = threadIdx.y;   // 32 x 8
    int l0 = blockIdx.x * 64, h0 = blockIdx.y * 32, b = blockIdx.z;
    const float* xb = x + (size_t)b * LL * HH;
#pragma unroll
    for (int i = 0; i < 8; i++)
        t[ty + i * 8][tx] = xb[(size_t)(l0 + ty + i * 8) * HH + h0 + tx];
    __syncthreads();
#pragma unroll
    for (int i = 0; i < 4; i++) {
        int hh = ty + i * 8;
        __half2 v = __floats2half2_rn(t[2 * tx][hh], t[2 * tx + 1][hh]);
        *(__half2*)&xt[(size_t)(h0 + hh) * (BB * LL) + (size_t)b * LL + l0 +
                       2 * tx] = v;
    }
}

// ---------------------------------------------------------------------------
// Kernel 2: Toeplitz tensor-core causal conv, NO T materialization.
// (EXACT R14 winner.)
// ---------------------------------------------------------------------------
#define XP 2064                       // x smem pitch (1024 fp16 + 8 pad)
#define SM_X 0                        // 16 * XP = 33024
#define SM_KS 33024                   // kern f32 [33024, 37120)
#define SM_KHD 37120                  // khd u32 [1104] -> [37120, 41536)
#define SM_EP 41536                   // 8 warps * 4352
#define SMEM_CONV 76352

__global__ __launch_bounds__(256, 2) void k_conv_tc(
    const __half* __restrict__ xt,
    const float* __restrict__ kern, const float* __restrict__ D,
    __half* __restrict__ yh) {
    extern __shared__ __align__(128) char smem[];
    uint32_t sb = smem_u32(smem);
    int tid = threadIdx.x;
    int wid = tid >> 5;
    int lane = tid & 31;
    int h = blockIdx.x;

    {
        const __half* s0 = xt + (size_t)h * (BB * LL);
        for (int i = tid; i < 2048; i += 256) {
            int b = i >> 7, g = i & 127;
            CP_ASYNC16(sb + SM_X + b * XP + g * 16, s0 + (size_t)b * LL + g * 8);
        }
    }
    CP_COMMIT();

    float* ks = (float*)(smem + SM_KS);
    for (int i = tid; i < 1024; i += 256) ks[i] = kern[(size_t)h * LL + i];
    __syncthreads();

    uint32_t* khd = (uint32_t*)(smem + SM_KHD);
    for (int i = tid; i < 1104; i += 256) {
        int u = i - 64;
        int j0 = u - 16, j1 = u - 17;
        float lo = (j0 >= 0 && j0 < 1024) ? ks[j0] : 0.0f;
        float hi = (j1 >= 0 && j1 < 1024) ? ks[j1] : 0.0f;
        __half2 p = __floats2half2_rn(lo, hi);
        khd[i] = *(uint32_t*)&p;
    }
    CP_WAIT0();
    __syncthreads();

    float acc[2][4][2][4];
#pragma unroll
    for (int t = 0; t < 2; t++)
#pragma unroll
        for (int mf = 0; mf < 4; mf++)
#pragma unroll
            for (int nf = 0; nf < 2; nf++)
#pragma unroll
                for (int e = 0; e < 4; e++) acc[t][mf][nf][e] = 0.0f;

    int li0 = wid;
    int li1 = 15 - wid;
    int lanebase = (lane >> 2) - 2 * (lane & 3);

#pragma unroll 1
    for (int d = 0; d <= li1; d++) {
        uint32_t kv[15];
        int b0 = 64 + 16 + 64 * d + lanebase;
#pragma unroll
        for (int j = 0; j < 15; j++) kv[j] = khd[b0 + 8 * (j - 7)];
#pragma unroll
        for (int t = 0; t < 2; t++) {
            int li = t ? li1 : li0;
            if (li < d) continue;
            int ji = li - d;
#pragma unroll
            for (int kc = 0; kc < 4; kc++) {
                uint32_t bh[2][2];
                uint32_t boff = (((lane >> 4) & 1) * 8 + (lane & 7)) * XP +
                                ji * 128 + kc * 32 + ((lane >> 3) & 1) * 16;
                {
                    uint32_t t4[4];
                    ldsm_x4(t4, sb + SM_X + boff);
                    bh[0][0] = t4[0]; bh[0][1] = t4[1];
                    bh[1][0] = t4[2]; bh[1][1] = t4[3];
                }
#pragma unroll
                for (int mf = 0; mf < 4; mf++) {
                    int idx = 7 + 2 * (mf - kc);
                    uint32_t a[4] = {kv[idx], kv[idx + 1], kv[idx - 1], kv[idx]};
                    mma_fp16(acc[t][mf][0], a, bh[0]);
                    mma_fp16(acc[t][mf][1], a, bh[1]);
                }
            }
        }
    }

    float Dh = D[h];
    float* epf = (float*)(smem + SM_EP + wid * 4352);
#pragma unroll 1
    for (int t = 0; t < 2; t++) {
        int li = t ? li1 : li0;
        int r0 = lane >> 2, cc = (lane & 3) * 2;
#pragma unroll
        for (int mf = 0; mf < 4; mf++)
#pragma unroll
            for (int nf = 0; nf < 2; nf++) {
                int bq = nf * 8 + cc;
                int lq = mf * 16 + r0;
                epf[bq * 68 + lq]           = acc[t][mf][nf][0];
                epf[(bq + 1) * 68 + lq]     = acc[t][mf][nf][1];
                epf[bq * 68 + lq + 8]       = acc[t][mf][nf][2];
                epf[(bq + 1) * 68 + lq + 8] = acc[t][mf][nf][3];
            }
        __syncwarp();
#pragma unroll
        for (int i = lane; i < 1024; i += 32) {
            int b = i >> 6, l = i & 63;
            int lout = li * 64 + l;
            float xv = __half2float(*(__half*)(smem + SM_X + b * XP + lout * 2));
            float v = gelu_tanh(epf[b * 68 + l] + xv * Dh);
            size_t o = (size_t)h * (BB * LL) + (size_t)b * LL + lout;
            yh[o] = __float2half(v);
        }
        __syncwarp();
    }
}

// ---------------------------------------------------------------------------
// Kernel 3: mma.sync fp16 1-term GEMM + bias + GLU.
// NEW: 3-buffer ring, ONE __syncthreads per k-stage:
//   wait_group(1) -> barrier (publish stage s) -> issue stage s+2 -> compute s.
// Hazards: issue into (s+2)%3 == (s-1)%3 happens after the stage-s barrier,
// which all stage-(s-1) readers have passed. 2 CTAs/SM (smem 105KB x 2 fits).
// ---------------------------------------------------------------------------
#define GAP 272                         // A smem pitch (128 m fp16 + 8 pad)
#define GABUF (64 * GAP)                // 17408
#define GBP 144                         // B smem pitch (64 k fp16 + 8 pad)
#define GBBUF (128 * GBP)               // 18432
#define SM_GA 0                         // [3 buf][GABUF] = 52224
#define SM_GB 52224                     // [3 buf][GBBUF] = 55296
#define SMEM_GEMM 107520
#define GNS 16                          // K stages (1024/64)

__global__ __launch_bounds__(256, 2) void k_gemm_mma(
    const __half* __restrict__ Yh, const __half* __restrict__ WT,
    const float* __restrict__ bias, float* __restrict__ out) {
    extern __shared__ __align__(128) char smem[];
    uint32_t sb = smem_u32(smem);
    int tid = threadIdx.x;
    int wid = tid >> 5;
    int lane = tid & 31;
    int wm = wid >> 2;                  // 0/1 -> m half (64 each)
    int wn = wid & 3;                   // 0..3 -> 32 B-rows each
    int N0a = blockIdx.x * 64;          // 64 output cols per CTA
    int M0 = blockIdx.y * 128;

    float acc[4][4][4];
#pragma unroll
    for (int i = 0; i < 4; i++)
#pragma unroll
        for (int j = 0; j < 4; j++)
#pragma unroll
            for (int e = 0; e < 4; e++) acc[i][j][e] = 0.0f;

#define G_ISSUE(S)                                                              \
    {                                                                           \
        int _s = (S);                                                           \
        int _buf = _s % 3;                                                      \
        int K0 = _s * 64;                                                       \
        _Pragma("unroll") for (int it = 0; it < 8; it++) {                      \
            int i = tid + it * 256;                                             \
            const __half* src;                                                  \
            uint32_t dst;                                                       \
            if (i < 1024) {                                                     \
                int r = i >> 4, g = i & 15;                                     \
                src = Yh + (size_t)(K0 + r) * 16384 + M0 + g * 8;               \
                dst = sb + SM_GA + _buf * GABUF + r * GAP + g * 16;             \
            } else {                                                            \
                int j = i - 1024;                                               \
                int rr = j >> 3, g = j & 7;                                     \
                int n = (rr & 1) ? (1024 + N0a + (rr >> 1)) : (N0a + (rr >> 1));\
                src = WT + (size_t)n * 1024 + K0 + g * 8;                       \
                dst = sb + SM_GB + _buf * GBBUF + rr * GBP + g * 16;            \
            }                                                                   \
            CP_ASYNC16(dst, src);                                               \
        }                                                                       \
        CP_COMMIT();                                                            \
    }

    G_ISSUE(0);
    G_ISSUE(1);
#pragma unroll 1
    for (int s = 0; s < GNS; s++) {
        int buf = s % 3;
        if (s + 1 < GNS) {
            CP_WAIT1();               // stage s groups complete (<=1 pending)
        } else {
            CP_WAIT0();
        }
        __syncthreads();              // publish stage s; fence stage s-1 readers
        if (s + 2 < GNS) G_ISSUE(s + 2);

        uint32_t aHb = sb + SM_GA + buf * GABUF;
        uint32_t bHb = sb + SM_GB + buf * GBBUF;

#pragma unroll
        for (int kc = 0; kc < 4; kc++) {
            uint32_t a_h[4][4];
            uint32_t arow = (kc * 16 + ((lane >> 4) & 1) * 8 + (lane & 7)) * GAP;
#pragma unroll
            for (int mf = 0; mf < 4; mf++) {
                uint32_t ao = arow + (wm * 64 + mf * 16 + ((lane >> 3) & 1) * 8) * 2;
                ldsm_x4t(a_h[mf], aHb + ao);
            }
            uint32_t boff = (((lane >> 4) & 1) * 8 + (lane & 7)) * GBP +
                            kc * 32 + ((lane >> 3) & 1) * 16;
#pragma unroll
            for (int q = 0; q < 2; q++) {
                uint32_t badr = (wn * 32 + q * 16) * GBP + boff;
                uint32_t bh[2][2];
                uint32_t t4[4];
                ldsm_x4(t4, bHb + badr);
                bh[0][0] = t4[0]; bh[0][1] = t4[1];
                bh[1][0] = t4[2]; bh[1][1] = t4[3];
#pragma unroll
                for (int mf = 0; mf < 4; mf++)
#pragma unroll
                    for (int e = 0; e < 2; e++)
                        mma_fp16(acc[mf][2 * q + e], a_h[mf], bh[e]);
            }
        }
    }

    // epilogue: bias + GLU (even B-row = a, odd = g, register-local pair)
#pragma unroll
    for (int nf = 0; nf < 4; nf++) {
        int p = wn * 16 + nf * 4 + (lane & 3);
        int col = N0a + p;
        float ba = bias[col];
        float bg = bias[1024 + col];
#pragma unroll
        for (int mf = 0; mf < 4; mf++) {
            int m = M0 + wm * 64 + mf * 16 + (lane >> 2);
            float a0 = acc[mf][nf][0] + ba;
            float g0 = acc[mf][nf][1] + bg;
            float a1 = acc[mf][nf][2] + ba;
            float g1 = acc[mf][nf][3] + bg;
            out[(size_t)m * 1024 + col]       = a0 / (1.0f + expf(-g0));
            out[(size_t)(m + 8) * 1024 + col] = a1 / (1.0f + expf(-g1));
        }
    }
}

// ---------------------------------------------------------------------------
extern "C" void kernel_launch(void* const* d_in, const int* in_sizes, int n_in,
                              void* d_out, int out_size) {
    const float* x      = (const float*)d_in[0];
    const float* log_dt = (const float*)d_in[1];
    const float* Arl    = (const float*)d_in[2];
    const float* Aim    = (const float*)d_in[3];
    const float* Cr     = (const float*)d_in[4];
    const float* Ci     = (const float*)d_in[5];
    const float* D      = (const float*)d_in[6];
    const float* W      = (const float*)d_in[7];
    const float* bias   = (const float*)d_in[8];
    float* out = (float*)d_out;

    float* kern;
    __half *xt, *yh, *wT;
    cudaGetSymbolAddress((void**)&kern, g_kern);
    cudaGetSymbolAddress((void**)&xt, g_xt);
    cudaGetSymbolAddress((void**)&yh, g_yh);
    cudaGetSymbolAddress((void**)&wT, g_wT);

    cudaFuncSetAttribute(k_conv_tc, cudaFuncAttributeMaxDynamicSharedMemorySize,
                         SMEM_CONV);
    cudaFuncSetAttribute(k_gemm_mma, cudaFuncAttributeMaxDynamicSharedMemorySize,
                         SMEM_GEMM);

    k_gen<<<dim3(HH, LL / GCH), 32>>>(log_dt, Arl, Aim, Cr, Ci, kern);
    k_prepW<<<dim3(2048 / 32, 1024 / 32), dim3(32, 8)>>>(W, wT);
    k_xt<<<dim3(LL / 64, HH / 32, BB), dim3(32, 8)>>>(x, xt);

    k_conv_tc<<<HH, 256, SMEM_CONV>>>(xt, kern, D, yh);

    dim3 ggrid(1024 / 64, 16384 / 128);   // (16, 128)
    k_gemm_mma<<<ggrid, 256, SMEM_GEMM>>>(yh, wT, bias, out);
}

// round 16
// speedup vs baseline: 2.8926x; 1.0057x over previous
#include <cuda_runtime.h>
#include <cuda_bf16.h>
#include <cuda_fp16.h>
#include <math.h>
#include <stdint.h>

#define BB 16
#define LL 1024
#define HH 1024
#define NN 64

// scratch (device globals — no allocation allowed)
__device__ float g_kern[HH * LL];              // kern [h][l]
__device__ __half g_xt[HH * BB * LL];          // x^T fp16 [h][b][l]
__device__ __half g_yh[HH * BB * LL];          // y^T fp16 [h][b*l] (k-major)
__device__ __half g_wT[2048 * 1024];           // W^T fp16 [n][k]

// ---- helpers ----------------------------------------------------------------
__device__ __forceinline__ uint32_t smem_u32(const void* p) {
    uint32_t a;
    asm("{ .reg .u64 t; cvta.to.shared.u64 t, %1; cvt.u32.u64 %0, t; }"
        : "=r"(a) : "l"(p));
    return a;
}
#define CP_ASYNC16(dst, src) \
    asm volatile("cp.async.cg.shared.global [%0], [%1], 16;" :: "r"(dst), "l"(src))
#define CP_COMMIT() asm volatile("cp.async.commit_group;" ::: "memory")
#define CP_WAIT1() asm volatile("cp.async.wait_group 1;" ::: "memory")
#define CP_WAIT0() asm volatile("cp.async.wait_group 0;" ::: "memory")

__device__ __forceinline__ void ldsm_x4(uint32_t* r, uint32_t addr) {
    asm volatile("ldmatrix.sync.aligned.m8n8.x4.shared.b16 {%0,%1,%2,%3}, [%4];"
                 : "=r"(r[0]), "=r"(r[1]), "=r"(r[2]), "=r"(r[3]) : "r"(addr));
}
__device__ __forceinline__ void ldsm_x4t(uint32_t* r, uint32_t addr) {
    asm volatile("ldmatrix.sync.aligned.m8n8.x4.trans.shared.b16 {%0,%1,%2,%3}, [%4];"
                 : "=r"(r[0]), "=r"(r[1]), "=r"(r[2]), "=r"(r[3]) : "r"(addr));
}
__device__ __forceinline__ void mma_fp16(float* c, const uint32_t* a,
                                         const uint32_t* b) {
    asm volatile(
        "mma.sync.aligned.m16n8k16.row.col.f32.f16.f16.f32 "
        "{%0,%1,%2,%3}, {%4,%5,%6,%7}, {%8,%9}, {%0,%1,%2,%3};"
        : "+f"(c[0]), "+f"(c[1]), "+f"(c[2]), "+f"(c[3])
        : "r"(a[0]), "r"(a[1]), "r"(a[2]), "r"(a[3]), "r"(b[0]), "r"(b[1]));
}
__device__ __forceinline__ float gelu_tanh(float t) {
    float c = 0.7978845608028654f * (t + 0.044715f * t * t * t);
    return 0.5f * t * (1.0f + tanhf(c));
}

// ---------------------------------------------------------------------------
// Kernel 1: S4D kernel generation, L-chunked (8 chunks of 128 per h).
// ---------------------------------------------------------------------------
#define GCH 128

__global__ void k_gen(const float* __restrict__ log_dt,
                      const float* __restrict__ Arl,
                      const float* __restrict__ Aim,
                      const float* __restrict__ Cr,
                      const float* __restrict__ Ci,
                      float* __restrict__ kern) {
    int h = blockIdx.x;
    int l0 = blockIdx.y * GCH;
    int lane = threadIdx.x;
    float dt = expf(log_dt[h]);

    float zr[2], zi[2], wr[2], wi[2];
#pragma unroll
    for (int t = 0; t < 2; t++) {
        int n = lane + t * 32;
        float ar = -expf(Arl[h * NN + n]);
        float ai = Aim[h * NN + n];
        float dr = dt * ar, di = dt * ai;
        float er = expf(dr);
        float sn, cs;
        sincosf(di, &sn, &cs);
        float Er = er * cs - 1.0f, Ei = er * sn;
        float inv = 1.0f / (ar * ar + ai * ai);
        float Fr = (Er * ar + Ei * ai) * inv;
        float Fi = (Ei * ar - Er * ai) * inv;
        float cr = Cr[h * NN + n], ci = Ci[h * NN + n];
        float c0r = cr * Fr - ci * Fi;
        float c0i = cr * Fi + ci * Fr;
        float e0 = expf(dr * (float)l0);
        float s0, q0;
        sincosf(di * (float)l0, &s0, &q0);
        float pr = e0 * q0, pi = e0 * s0;
        zr[t] = c0r * pr - c0i * pi;
        zi[t] = c0r * pi + c0i * pr;
        wr[t] = er * cs;
        wi[t] = er * sn;
    }
    float* kout = kern + (size_t)h * LL + l0;
    for (int l = 0; l < GCH; l++) {
        float s = zr[0] + zr[1];
#pragma unroll
        for (int o = 16; o > 0; o >>= 1)
            s += __shfl_xor_sync(0xffffffffu, s, o);
        if (lane == 0) kout[l] = 2.0f * s;
#pragma unroll
        for (int t = 0; t < 2; t++) {
            float tr = zr[t] * wr[t] - zi[t] * wi[t];
            zi[t] = zr[t] * wi[t] + zi[t] * wr[t];
            zr[t] = tr;
        }
    }
}

// ---------------------------------------------------------------------------
// Kernel 1b: W [1024,2048] -> W^T fp16 [2048][1024]
// ---------------------------------------------------------------------------
__global__ void k_prepW(const float* __restrict__ W, __half* __restrict__ wT) {
    __shared__ float t[32][33];
    int tx = threadIdx.x, ty = threadIdx.y;
    int n0 = blockIdx.x * 32, k0 = blockIdx.y * 32;
#pragma unroll
    for (int i = 0; i < 4; i++)
        t[ty + i * 8][tx] = W[(size_t)(k0 + ty + i * 8) * 2048 + n0 + tx];
    __syncthreads();
#pragma unroll
    for (int i = 0; i < 4; i++) {
        int n = n0 + ty + i * 8;
        wT[(size_t)n * 1024 + k0 + tx] = __float2half(t[tx][ty + i * 8]);
    }
}

// ---------------------------------------------------------------------------
// Kernel 1c: x [b][l][h] f32 -> x^T fp16 [h][b][l]. 64l x 32h tiles,
// __half2 stores.
// ---------------------------------------------------------------------------
__global__ void k_xt(const float* __restrict__ x, __half* __restrict__ xt) {
    __shared__ float t[64][33];
    int tx = threadIdx.x, ty = threadIdx.y;   // 32 x 8
    int l0 = blockIdx.x * 64, h0 = blockIdx.y * 32, b = blockIdx.z;
    const float* xb = x + (size_t)b * LL * HH;
#pragma unroll
    for (int i = 0; i < 8; i++)
        t[ty + i * 8][tx] = xb[(size_t)(l0 + ty + i * 8) * HH + h0 + tx];
    __syncthreads();
#pragma unroll
    for (int i = 0; i < 4; i++) {
        int hh = ty + i * 8;
        __half2 v = __floats2half2_rn(t[2 * tx][hh], t[2 * tx + 1][hh]);
        *(__half2*)&xt[(size_t)(h0 + hh) * (BB * LL) + (size_t)b * LL + l0 +
                       2 * tx] = v;
    }
}

// ---------------------------------------------------------------------------
// Kernel 2: Toeplitz tensor-core causal conv, NO T materialization.
// R14 mainloop; epilogue vectorized this round (half2 loads/stores, float2
// epf reads -> 128B store wavefronts, half the iterations).
// ---------------------------------------------------------------------------
#define XP 2064                       // x smem pitch (1024 fp16 + 8 pad)
#define SM_X 0                        // 16 * XP = 33024
#define SM_KS 33024                   // kern f32 [33024, 37120)
#define SM_KHD 37120                  // khd u32 [1104] -> [37120, 41536)
#define SM_EP 41536                   // 8 warps * 4352
#define SMEM_CONV 76352

__global__ __launch_bounds__(256, 2) void k_conv_tc(
    const __half* __restrict__ xt,
    const float* __restrict__ kern, const float* __restrict__ D,
    __half* __restrict__ yh) {
    extern __shared__ __align__(128) char smem[];
    uint32_t sb = smem_u32(smem);
    int tid = threadIdx.x;
    int wid = tid >> 5;
    int lane = tid & 31;
    int h = blockIdx.x;

    {
        const __half* s0 = xt + (size_t)h * (BB * LL);
        for (int i = tid; i < 2048; i += 256) {
            int b = i >> 7, g = i & 127;
            CP_ASYNC16(sb + SM_X + b * XP + g * 16, s0 + (size_t)b * LL + g * 8);
        }
    }
    CP_COMMIT();

    float* ks = (float*)(smem + SM_KS);
    for (int i = tid; i < 1024; i += 256) ks[i] = kern[(size_t)h * LL + i];
    __syncthreads();

    uint32_t* khd = (uint32_t*)(smem + SM_KHD);
    for (int i = tid; i < 1104; i += 256) {
        int u = i - 64;
        int j0 = u - 16, j1 = u - 17;
        float lo = (j0 >= 0 && j0 < 1024) ? ks[j0] : 0.0f;
        float hi = (j1 >= 0 && j1 < 1024) ? ks[j1] : 0.0f;
        __half2 p = __floats2half2_rn(lo, hi);
        khd[i] = *(uint32_t*)&p;
    }
    CP_WAIT0();
    __syncthreads();

    float acc[2][4][2][4];
#pragma unroll
    for (int t = 0; t < 2; t++)
#pragma unroll
        for (int mf = 0; mf < 4; mf++)
#pragma unroll
            for (int nf = 0; nf < 2; nf++)
#pragma unroll
                for (int e = 0; e < 4; e++) acc[t][mf][nf][e] = 0.0f;

    int li0 = wid;
    int li1 = 15 - wid;
    int lanebase = (lane >> 2) - 2 * (lane & 3);

#pragma unroll 1
    for (int d = 0; d <= li1; d++) {
        uint32_t kv[15];
        int b0 = 64 + 16 + 64 * d + lanebase;
#pragma unroll
        for (int j = 0; j < 15; j++) kv[j] = khd[b0 + 8 * (j - 7)];
#pragma unroll
        for (int t = 0; t < 2; t++) {
            int li = t ? li1 : li0;
            if (li < d) continue;
            int ji = li - d;
#pragma unroll
            for (int kc = 0; kc < 4; kc++) {
                uint32_t bh[2][2];
                uint32_t boff = (((lane >> 4) & 1) * 8 + (lane & 7)) * XP +
                                ji * 128 + kc * 32 + ((lane >> 3) & 1) * 16;
                {
                    uint32_t t4[4];
                    ldsm_x4(t4, sb + SM_X + boff);
                    bh[0][0] = t4[0]; bh[0][1] = t4[1];
                    bh[1][0] = t4[2]; bh[1][1] = t4[3];
                }
#pragma unroll
                for (int mf = 0; mf < 4; mf++) {
                    int idx = 7 + 2 * (mf - kc);
                    uint32_t a[4] = {kv[idx], kv[idx + 1], kv[idx - 1], kv[idx]};
                    mma_fp16(acc[t][mf][0], a, bh[0]);
                    mma_fp16(acc[t][mf][1], a, bh[1]);
                }
            }
        }
    }

    float Dh = D[h];
    float* epf = (float*)(smem + SM_EP + wid * 4352);   // per-warp exclusive
#pragma unroll 1
    for (int t = 0; t < 2; t++) {
        int li = t ? li1 : li0;
        int r0 = lane >> 2, cc = (lane & 3) * 2;
#pragma unroll
        for (int mf = 0; mf < 4; mf++)
#pragma unroll
            for (int nf = 0; nf < 2; nf++) {
                int bq = nf * 8 + cc;
                int lq = mf * 16 + r0;
                epf[bq * 68 + lq]           = acc[t][mf][nf][0];
                epf[(bq + 1) * 68 + lq]     = acc[t][mf][nf][1];
                epf[bq * 68 + lq + 8]       = acc[t][mf][nf][2];
                epf[(bq + 1) * 68 + lq + 8] = acc[t][mf][nf][3];
            }
        __syncwarp();
        // vectorized: each lane handles 2 consecutive l (half2/float2)
#pragma unroll
        for (int i = lane; i < 512; i += 32) {
            int b = i >> 5, l = (i & 31) * 2;
            int lout = li * 64 + l;
            float2 cv = *(float2*)&epf[b * 68 + l];
            __half2 xv = *(__half2*)(smem + SM_X + b * XP + lout * 2);
            float v0 = gelu_tanh(cv.x + __low2float(xv) * Dh);
            float v1 = gelu_tanh(cv.y + __high2float(xv) * Dh);
            size_t o = (size_t)h * (BB * LL) + (size_t)b * LL + lout;
            *(__half2*)&yh[o] = __floats2half2_rn(v0, v1);
        }
        __syncwarp();
    }
}

// ---------------------------------------------------------------------------
// Kernel 3: mma.sync fp16 1-term GEMM + bias + GLU.
// (R15 structure: 3-buffer ring, one barrier per stage, 2 CTAs/SM.)
// ---------------------------------------------------------------------------
#define GAP 272                         // A smem pitch (128 m fp16 + 8 pad)
#define GABUF (64 * GAP)                // 17408
#define GBP 144                         // B smem pitch (64 k fp16 + 8 pad)
#define GBBUF (128 * GBP)               // 18432
#define SM_GA 0                         // [3 buf][GABUF] = 52224
#define SM_GB 52224                     // [3 buf][GBBUF] = 55296
#define SMEM_GEMM 107520
#define GNS 16                          // K stages (1024/64)

__global__ __launch_bounds__(256, 2) void k_gemm_mma(
    const __half* __restrict__ Yh, const __half* __restrict__ WT,
    const float* __restrict__ bias, float* __restrict__ out) {
    extern __shared__ __align__(128) char smem[];
    uint32_t sb = smem_u32(smem);
    int tid = threadIdx.x;
    int wid = tid >> 5;
    int lane = tid & 31;
    int wm = wid >> 2;                  // 0/1 -> m half (64 each)
    int wn = wid & 3;                   // 0..3 -> 32 B-rows each
    int N0a = blockIdx.x * 64;          // 64 output cols per CTA
    int M0 = blockIdx.y * 128;

    float acc[4][4][4];
#pragma unroll
    for (int i = 0; i < 4; i++)
#pragma unroll
        for (int j = 0; j < 4; j++)
#pragma unroll
            for (int e = 0; e < 4; e++) acc[i][j][e] = 0.0f;

#define G_ISSUE(S)                                                              \
    {                                                                           \
        int _s = (S);                                                           \
        int _buf = _s % 3;                                                      \
        int K0 = _s * 64;                                                       \
        _Pragma("unroll") for (int it = 0; it < 8; it++) {                      \
            int i = tid + it * 256;                                             \
            const __half* src;                                                  \
            uint32_t dst;                                                       \
            if (i < 1024) {                                                     \
                int r = i >> 4, g = i & 15;                                     \
                src = Yh + (size_t)(K0 + r) * 16384 + M0 + g * 8;               \
                dst = sb + SM_GA + _buf * GABUF + r * GAP + g * 16;             \
            } else {                                                            \
                int j = i - 1024;                                               \
                int rr = j >> 3, g = j & 7;                                     \
                int n = (rr & 1) ? (1024 + N0a + (rr >> 1)) : (N0a + (rr >> 1));\
                src = WT + (size_t)n * 1024 + K0 + g * 8;                       \
                dst = sb + SM_GB + _buf * GBBUF + rr * GBP + g * 16;            \
            }                                                                   \
            CP_ASYNC16(dst, src);                                               \
        }                                                                       \
        CP_COMMIT();                                                            \
    }

    G_ISSUE(0);
    G_ISSUE(1);
#pragma unroll 1
    for (int s = 0; s < GNS; s++) {
        int buf = s % 3;
        if (s + 1 < GNS) {
            CP_WAIT1();
        } else {
            CP_WAIT0();
        }
        __syncthreads();
        if (s + 2 < GNS) G_ISSUE(s + 2);

        uint32_t aHb = sb + SM_GA + buf * GABUF;
        uint32_t bHb = sb + SM_GB + buf * GBBUF;

#pragma unroll
        for (int kc = 0; kc < 4; kc++) {
            uint32_t a_h[4][4];
            uint32_t arow = (kc * 16 + ((lane >> 4) & 1) * 8 + (lane & 7)) * GAP;
#pragma unroll
            for (int mf = 0; mf < 4; mf++) {
                uint32_t ao = arow + (wm * 64 + mf * 16 + ((lane >> 3) & 1) * 8) * 2;
                ldsm_x4t(a_h[mf], aHb + ao);
            }
            uint32_t boff = (((lane >> 4) & 1) * 8 + (lane & 7)) * GBP +
                            kc * 32 + ((lane >> 3) & 1) * 16;
#pragma unroll
            for (int q = 0; q < 2; q++) {
                uint32_t badr = (wn * 32 + q * 16) * GBP + boff;
                uint32_t bh[2][2];
                uint32_t t4[4];
                ldsm_x4(t4, bHb + badr);
                bh[0][0] = t4[0]; bh[0][1] = t4[1];
                bh[1][0] = t4[2]; bh[1][1] = t4[3];
#pragma unroll
                for (int mf = 0; mf < 4; mf++)
#pragma unroll
                    for (int e = 0; e < 2; e++)
                        mma_fp16(acc[mf][2 * q + e], a_h[mf], bh[e]);
            }
        }
    }

    // epilogue: bias + GLU (even B-row = a, odd = g, register-local pair)
#pragma unroll
    for (int nf = 0; nf < 4; nf++) {
        int p = wn * 16 + nf * 4 + (lane & 3);
        int col = N0a + p;
        float ba = bias[col];
        float bg = bias[1024 + col];
#pragma unroll
        for (int mf = 0; mf < 4; mf++) {
            int m = M0 + wm * 64 + mf * 16 + (lane >> 2);
            float a0 = acc[mf][nf][0] + ba;
            float g0 = acc[mf][nf][1] + bg;
            float a1 = acc[mf][nf][2] + ba;
            float g1 = acc[mf][nf][3] + bg;
            out[(size_t)m * 1024 + col]       = a0 / (1.0f + expf(-g0));
            out[(size_t)(m + 8) * 1024 + col] = a1 / (1.0f + expf(-g1));
        }
    }
}

// ---------------------------------------------------------------------------
extern "C" void kernel_launch(void* const* d_in, const int* in_sizes, int n_in,
                              void* d_out, int out_size) {
    const float* x      = (const float*)d_in[0];
    const float* log_dt = (const float*)d_in[1];
    const float* Arl    = (const float*)d_in[2];
    const float* Aim    = (const float*)d_in[3];
    const float* Cr     = (const float*)d_in[4];
    const float* Ci     = (const float*)d_in[5];
    const float* D      = (const float*)d_in[6];
    const float* W      = (const float*)d_in[7];
    const float* bias   = (const float*)d_in[8];
    float* out = (float*)d_out;

    float* kern;
    __half *xt, *yh, *wT;
    cudaGetSymbolAddress((void**)&kern, g_kern);
    cudaGetSymbolAddress((void**)&xt, g_xt);
    cudaGetSymbolAddress((void**)&yh, g_yh);
    cudaGetSymbolAddress((void**)&wT, g_wT);

    cudaFuncSetAttribute(k_conv_tc, cudaFuncAttributeMaxDynamicSharedMemorySize,
                         SMEM_CONV);
    cudaFuncSetAttribute(k_gemm_mma, cudaFuncAttributeMaxDynamicSharedMemorySize,
                         SMEM_GEMM);

    k_gen<<<dim3(HH, LL / GCH), 32>>>(log_dt, Arl, Aim, Cr, Ci, kern);
    k_prepW<<<dim3(2048 / 32, 1024 / 32), dim3(32, 8)>>>(W, wT);
    k_xt<<<dim3(LL / 64, HH / 32, BB), dim3(32, 8)>>>(x, xt);

    k_conv_tc<<<HH, 256, SMEM_CONV>>>(xt, kern, D, yh);

    dim3 ggrid(1024 / 64, 16384 / 128);   // (16, 128)
    k_gemm_mma<<<ggrid, 256, SMEM_GEMM>>>(yh, wT, bias, out);
}

// round 17
// speedup vs baseline: 2.9726x; 1.0277x over previous
#include <cuda_runtime.h>
#include <cuda_bf16.h>
#include <cuda_fp16.h>
#include <math.h>
#include <stdint.h>

#define BB 16
#define LL 1024
#define HH 1024
#define NN 64

// scratch (device globals — no allocation allowed)
__device__ float g_kern[HH * LL];              // kern [h][l]
__device__ __half g_xt[HH * BB * LL];          // x^T fp16 [h][b][l]
__device__ __half g_yh[HH * BB * LL];          // y^T fp16 [h][b*l] (k-major)
__device__ __half g_wT[2048 * 1024];           // W^T fp16 [n][k]

// ---- helpers ----------------------------------------------------------------
__device__ __forceinline__ uint32_t smem_u32(const void* p) {
    uint32_t a;
    asm("{ .reg .u64 t; cvta.to.shared.u64 t, %1; cvt.u32.u64 %0, t; }"
        : "=r"(a) : "l"(p));
    return a;
}
#define CP_ASYNC16(dst, src) \
    asm volatile("cp.async.cg.shared.global [%0], [%1], 16;" :: "r"(dst), "l"(src))
#define CP_COMMIT() asm volatile("cp.async.commit_group;" ::: "memory")
#define CP_WAIT1() asm volatile("cp.async.wait_group 1;" ::: "memory")
#define CP_WAIT0() asm volatile("cp.async.wait_group 0;" ::: "memory")

__device__ __forceinline__ void ldsm_x4(uint32_t* r, uint32_t addr) {
    asm volatile("ldmatrix.sync.aligned.m8n8.x4.shared.b16 {%0,%1,%2,%3}, [%4];"
                 : "=r"(r[0]), "=r"(r[1]), "=r"(r[2]), "=r"(r[3]) : "r"(addr));
}
__device__ __forceinline__ void ldsm_x4t(uint32_t* r, uint32_t addr) {
    asm volatile("ldmatrix.sync.aligned.m8n8.x4.trans.shared.b16 {%0,%1,%2,%3}, [%4];"
                 : "=r"(r[0]), "=r"(r[1]), "=r"(r[2]), "=r"(r[3]) : "r"(addr));
}
__device__ __forceinline__ void mma_fp16(float* c, const uint32_t* a,
                                         const uint32_t* b) {
    asm volatile(
        "mma.sync.aligned.m16n8k16.row.col.f32.f16.f16.f32 "
        "{%0,%1,%2,%3}, {%4,%5,%6,%7}, {%8,%9}, {%0,%1,%2,%3};"
        : "+f"(c[0]), "+f"(c[1]), "+f"(c[2]), "+f"(c[3])
        : "r"(a[0]), "r"(a[1]), "r"(a[2]), "r"(a[3]), "r"(b[0]), "r"(b[1]));
}
__device__ __forceinline__ float gelu_tanh(float t) {
    float c = 0.7978845608028654f * (t + 0.044715f * t * t * t);
    return 0.5f * t * (1.0f + tanhf(c));
}

// ---------------------------------------------------------------------------
// Kernel 1 (FUSED PREP): gen + prepW + xt in one launch, partitioned by
// blockIdx.x. All three are mutually independent; fusing overlaps the
// MUFU-bound gen warps with the memory-bound transposes and removes two
// serialized launch/drain boundaries.
//   blocks [0, 1024):      k_gen    (8 independent warps per block)
//   blocks [1024, 3072):   k_prepW  (2048 blocks)
//   blocks [3072, 11264):  k_xt     (8192 blocks)
// ---------------------------------------------------------------------------
#define GCH 128

__global__ __launch_bounds__(256) void k_prep(
    const float* __restrict__ log_dt,
    const float* __restrict__ Arl,
    const float* __restrict__ Aim,
    const float* __restrict__ Cr,
    const float* __restrict__ Ci,
    const float* __restrict__ W,
    const float* __restrict__ x,
    float* __restrict__ kern,
    __half* __restrict__ wT,
    __half* __restrict__ xt) {
    __shared__ float t[64][33];
    int blk = blockIdx.x;
    int tid = threadIdx.x;

    if (blk < 1024) {
        // ---- gen: one warp per (h, l0-chunk) ----
        int lane = tid & 31;
        int g = blk * 8 + (tid >> 5);
        int h = g >> 3;
        int l0 = (g & 7) * GCH;
        float dt = expf(log_dt[h]);

        float zr[2], zi[2], wr[2], wi[2];
#pragma unroll
        for (int tt = 0; tt < 2; tt++) {
            int n = lane + tt * 32;
            float ar = -expf(Arl[h * NN + n]);
            float ai = Aim[h * NN + n];
            float dr = dt * ar, di = dt * ai;
            float er = expf(dr);
            float sn, cs;
            sincosf(di, &sn, &cs);
            float Er = er * cs - 1.0f, Ei = er * sn;
            float inv = 1.0f / (ar * ar + ai * ai);
            float Fr = (Er * ar + Ei * ai) * inv;
            float Fi = (Ei * ar - Er * ai) * inv;
            float cr = Cr[h * NN + n], ci = Ci[h * NN + n];
            float c0r = cr * Fr - ci * Fi;
            float c0i = cr * Fi + ci * Fr;
            float e0 = expf(dr * (float)l0);
            float s0, q0;
            sincosf(di * (float)l0, &s0, &q0);
            float pr = e0 * q0, pi = e0 * s0;
            zr[tt] = c0r * pr - c0i * pi;
            zi[tt] = c0r * pi + c0i * pr;
            wr[tt] = er * cs;
            wi[tt] = er * sn;
        }
        float* kout = kern + (size_t)h * LL + l0;
        for (int l = 0; l < GCH; l++) {
            float s = zr[0] + zr[1];
#pragma unroll
            for (int o = 16; o > 0; o >>= 1)
                s += __shfl_xor_sync(0xffffffffu, s, o);
            if (lane == 0) kout[l] = 2.0f * s;
#pragma unroll
            for (int tt = 0; tt < 2; tt++) {
                float tr = zr[tt] * wr[tt] - zi[tt] * wi[tt];
                zi[tt] = zr[tt] * wi[tt] + zi[tt] * wr[tt];
                zr[tt] = tr;
            }
        }
    } else if (blk < 3072) {
        // ---- prepW: W [1024,2048] f32 -> W^T fp16 [2048][1024] ----
        int idx = blk - 1024;
        int tx = tid & 31, ty = tid >> 5;
        int n0 = (idx & 63) * 32, k0 = (idx >> 6) * 32;
#pragma unroll
        for (int i = 0; i < 4; i++)
            t[ty + i * 8][tx] = W[(size_t)(k0 + ty + i * 8) * 2048 + n0 + tx];
        __syncthreads();
#pragma unroll
        for (int i = 0; i < 4; i++) {
            int n = n0 + ty + i * 8;
            wT[(size_t)n * 1024 + k0 + tx] = __float2half(t[tx][ty + i * 8]);
        }
    } else {
        // ---- xt: x [b][l][h] f32 -> x^T fp16 [h][b][l] ----
        int idx = blk - 3072;
        int tx = tid & 31, ty = tid >> 5;
        int l0 = (idx & 15) * 64;
        int h0 = ((idx >> 4) & 31) * 32;
        int b = idx >> 9;
        const float* xb = x + (size_t)b * LL * HH;
#pragma unroll
        for (int i = 0; i < 8; i++)
            t[ty + i * 8][tx] = xb[(size_t)(l0 + ty + i * 8) * HH + h0 + tx];
        __syncthreads();
#pragma unroll
        for (int i = 0; i < 4; i++) {
            int hh = ty + i * 8;
            __half2 v = __floats2half2_rn(t[2 * tx][hh], t[2 * tx + 1][hh]);
            *(__half2*)&xt[(size_t)(h0 + hh) * (BB * LL) + (size_t)b * LL + l0 +
                           2 * tx] = v;
        }
    }
}

// ---------------------------------------------------------------------------
// Kernel 2: Toeplitz tensor-core causal conv (EXACT R16 winner).
// ---------------------------------------------------------------------------
#define XP 2064                       // x smem pitch (1024 fp16 + 8 pad)
#define SM_X 0                        // 16 * XP = 33024
#define SM_KS 33024                   // kern f32 [33024, 37120)
#define SM_KHD 37120                  // khd u32 [1104] -> [37120, 41536)
#define SM_EP 41536                   // 8 warps * 4352
#define SMEM_CONV 76352

__global__ __launch_bounds__(256, 2) void k_conv_tc(
    const __half* __restrict__ xt,
    const float* __restrict__ kern, const float* __restrict__ D,
    __half* __restrict__ yh) {
    extern __shared__ __align__(128) char smem[];
    uint32_t sb = smem_u32(smem);
    int tid = threadIdx.x;
    int wid = tid >> 5;
    int lane = tid & 31;
    int h = blockIdx.x;

    {
        const __half* s0 = xt + (size_t)h * (BB * LL);
        for (int i = tid; i < 2048; i += 256) {
            int b = i >> 7, g = i & 127;
            CP_ASYNC16(sb + SM_X + b * XP + g * 16, s0 + (size_t)b * LL + g * 8);
        }
    }
    CP_COMMIT();

    float* ks = (float*)(smem + SM_KS);
    for (int i = tid; i < 1024; i += 256) ks[i] = kern[(size_t)h * LL + i];
    __syncthreads();

    uint32_t* khd = (uint32_t*)(smem + SM_KHD);
    for (int i = tid; i < 1104; i += 256) {
        int u = i - 64;
        int j0 = u - 16, j1 = u - 17;
        float lo = (j0 >= 0 && j0 < 1024) ? ks[j0] : 0.0f;
        float hi = (j1 >= 0 && j1 < 1024) ? ks[j1] : 0.0f;
        __half2 p = __floats2half2_rn(lo, hi);
        khd[i] = *(uint32_t*)&p;
    }
    CP_WAIT0();
    __syncthreads();

    float acc[2][4][2][4];
#pragma unroll
    for (int t = 0; t < 2; t++)
#pragma unroll
        for (int mf = 0; mf < 4; mf++)
#pragma unroll
            for (int nf = 0; nf < 2; nf++)
#pragma unroll
                for (int e = 0; e < 4; e++) acc[t][mf][nf][e] = 0.0f;

    int li0 = wid;
    int li1 = 15 - wid;
    int lanebase = (lane >> 2) - 2 * (lane & 3);

#pragma unroll 1
    for (int d = 0; d <= li1; d++) {
        uint32_t kv[15];
        int b0 = 64 + 16 + 64 * d + lanebase;
#pragma unroll
        for (int j = 0; j < 15; j++) kv[j] = khd[b0 + 8 * (j - 7)];
#pragma unroll
        for (int t = 0; t < 2; t++) {
            int li = t ? li1 : li0;
            if (li < d) continue;
            int ji = li - d;
#pragma unroll
            for (int kc = 0; kc < 4; kc++) {
                uint32_t bh[2][2];
                uint32_t boff = (((lane >> 4) & 1) * 8 + (lane & 7)) * XP +
                                ji * 128 + kc * 32 + ((lane >> 3) & 1) * 16;
                {
                    uint32_t t4[4];
                    ldsm_x4(t4, sb + SM_X + boff);
                    bh[0][0] = t4[0]; bh[0][1] = t4[1];
                    bh[1][0] = t4[2]; bh[1][1] = t4[3];
                }
#pragma unroll
                for (int mf = 0; mf < 4; mf++) {
                    int idx = 7 + 2 * (mf - kc);
                    uint32_t a[4] = {kv[idx], kv[idx + 1], kv[idx - 1], kv[idx]};
                    mma_fp16(acc[t][mf][0], a, bh[0]);
                    mma_fp16(acc[t][mf][1], a, bh[1]);
                }
            }
        }
    }

    float Dh = D[h];
    float* epf = (float*)(smem + SM_EP + wid * 4352);
#pragma unroll 1
    for (int t = 0; t < 2; t++) {
        int li = t ? li1 : li0;
        int r0 = lane >> 2, cc = (lane & 3) * 2;
#pragma unroll
        for (int mf = 0; mf < 4; mf++)
#pragma unroll
            for (int nf = 0; nf < 2; nf++) {
                int bq = nf * 8 + cc;
                int lq = mf * 16 + r0;
                epf[bq * 68 + lq]           = acc[t][mf][nf][0];
                epf[(bq + 1) * 68 + lq]     = acc[t][mf][nf][1];
                epf[bq * 68 + lq + 8]       = acc[t][mf][nf][2];
                epf[(bq + 1) * 68 + lq + 8] = acc[t][mf][nf][3];
            }
        __syncwarp();
#pragma unroll
        for (int i = lane; i < 512; i += 32) {
            int b = i >> 5, l = (i & 31) * 2;
            int lout = li * 64 + l;
            float2 cv = *(float2*)&epf[b * 68 + l];
            __half2 xv = *(__half2*)(smem + SM_X + b * XP + lout * 2);
            float v0 = gelu_tanh(cv.x + __low2float(xv) * Dh);
            float v1 = gelu_tanh(cv.y + __high2float(xv) * Dh);
            size_t o = (size_t)h * (BB * LL) + (size_t)b * LL + lout;
            *(__half2*)&yh[o] = __floats2half2_rn(v0, v1);
        }
        __syncwarp();
    }
}

// ---------------------------------------------------------------------------
// Kernel 3: mma.sync fp16 1-term GEMM + bias + GLU (EXACT R15/R16 winner).
// ---------------------------------------------------------------------------
#define GAP 272                         // A smem pitch (128 m fp16 + 8 pad)
#define GABUF (64 * GAP)                // 17408
#define GBP 144                         // B smem pitch (64 k fp16 + 8 pad)
#define GBBUF (128 * GBP)               // 18432
#define SM_GA 0                         // [3 buf][GABUF] = 52224
#define SM_GB 52224                     // [3 buf][GBBUF] = 55296
#define SMEM_GEMM 107520
#define GNS 16                          // K stages (1024/64)

__global__ __launch_bounds__(256, 2) void k_gemm_mma(
    const __half* __restrict__ Yh, const __half* __restrict__ WT,
    const float* __restrict__ bias, float* __restrict__ out) {
    extern __shared__ __align__(128) char smem[];
    uint32_t sb = smem_u32(smem);
    int tid = threadIdx.x;
    int wid = tid >> 5;
    int lane = tid & 31;
    int wm = wid >> 2;
    int wn = wid & 3;
    int N0a = blockIdx.x * 64;
    int M0 = blockIdx.y * 128;

    float acc[4][4][4];
#pragma unroll
    for (int i = 0; i < 4; i++)
#pragma unroll
        for (int j = 0; j < 4; j++)
#pragma unroll
            for (int e = 0; e < 4; e++) acc[i][j][e] = 0.0f;

#define G_ISSUE(S)                                                              \
    {                                                                           \
        int _s = (S);                                                           \
        int _buf = _s % 3;                                                      \
        int K0 = _s * 64;                                                       \
        _Pragma("unroll") for (int it = 0; it < 8; it++) {                      \
            int i = tid + it * 256;                                             \
            const __half* src;                                                  \
            uint32_t dst;                                                       \
            if (i < 1024) {                                                     \
                int r = i >> 4, g = i & 15;                                     \
                src = Yh + (size_t)(K0 + r) * 16384 + M0 + g * 8;               \
                dst = sb + SM_GA + _buf * GABUF + r * GAP + g * 16;             \
            } else {                                                            \
                int j = i - 1024;                                               \
                int rr = j >> 3, g = j & 7;                                     \
                int n = (rr & 1) ? (1024 + N0a + (rr >> 1)) : (N0a + (rr >> 1));\
                src = WT + (size_t)n * 1024 + K0 + g * 8;                       \
                dst = sb + SM_GB + _buf * GBBUF + rr * GBP + g * 16;            \
            }                                                                   \
            CP_ASYNC16(dst, src);                                               \
        }                                                                       \
        CP_COMMIT();                                                            \
    }

    G_ISSUE(0);
    G_ISSUE(1);
#pragma unroll 1
    for (int s = 0; s < GNS; s++) {
        int buf = s % 3;
        if (s + 1 < GNS) {
            CP_WAIT1();
        } else {
            CP_WAIT0();
        }
        __syncthreads();
        if (s + 2 < GNS) G_ISSUE(s + 2);

        uint32_t aHb = sb + SM_GA + buf * GABUF;
        uint32_t bHb = sb + SM_GB + buf * GBBUF;

#pragma unroll
        for (int kc = 0; kc < 4; kc++) {
            uint32_t a_h[4][4];
            uint32_t arow = (kc * 16 + ((lane >> 4) & 1) * 8 + (lane & 7)) * GAP;
#pragma unroll
            for (int mf = 0; mf < 4; mf++) {
                uint32_t ao = arow + (wm * 64 + mf * 16 + ((lane >> 3) & 1) * 8) * 2;
                ldsm_x4t(a_h[mf], aHb + ao);
            }
            uint32_t boff = (((lane >> 4) & 1) * 8 + (lane & 7)) * GBP +
                            kc * 32 + ((lane >> 3) & 1) * 16;
#pragma unroll
            for (int q = 0; q < 2; q++) {
                uint32_t badr = (wn * 32 + q * 16) * GBP + boff;
                uint32_t bh[2][2];
                uint32_t t4[4];
                ldsm_x4(t4, bHb + badr);
                bh[0][0] = t4[0]; bh[0][1] = t4[1];
                bh[1][0] = t4[2]; bh[1][1] = t4[3];
#pragma unroll
                for (int mf = 0; mf < 4; mf++)
#pragma unroll
                    for (int e = 0; e < 2; e++)
                        mma_fp16(acc[mf][2 * q + e], a_h[mf], bh[e]);
            }
        }
    }

#pragma unroll
    for (int nf = 0; nf < 4; nf++) {
        int p = wn * 16 + nf * 4 + (lane & 3);
        int col = N0a + p;
        float ba = bias[col];
        float bg = bias[1024 + col];
#pragma unroll
        for (int mf = 0; mf < 4; mf++) {
            int m = M0 + wm * 64 + mf * 16 + (lane >> 2);
            float a0 = acc[mf][nf][0] + ba;
            float g0 = acc[mf][nf][1] + bg;
            float a1 = acc[mf][nf][2] + ba;
            float g1 = acc[mf][nf][3] + bg;
            out[(size_t)m * 1024 + col]       = a0 / (1.0f + expf(-g0));
            out[(size_t)(m + 8) * 1024 + col] = a1 / (1.0f + expf(-g1));
        }
    }
}

// ---------------------------------------------------------------------------
extern "C" void kernel_launch(void* const* d_in, const int* in_sizes, int n_in,
                              void* d_out, int out_size) {
    const float* x      = (const float*)d_in[0];
    const float* log_dt = (const float*)d_in[1];
    const float* Arl    = (const float*)d_in[2];
    const float* Aim    = (const float*)d_in[3];
    const float* Cr     = (const float*)d_in[4];
    const float* Ci     = (const float*)d_in[5];
    const float* D      = (const float*)d_in[6];
    const float* W      = (const float*)d_in[7];
    const float* bias   = (const float*)d_in[8];
    float* out = (float*)d_out;

    float* kern;
    __half *xt, *yh, *wT;
    cudaGetSymbolAddress((void**)&kern, g_kern);
    cudaGetSymbolAddress((void**)&xt, g_xt);
    cudaGetSymbolAddress((void**)&yh, g_yh);
    cudaGetSymbolAddress((void**)&wT, g_wT);

    cudaFuncSetAttribute(k_conv_tc, cudaFuncAttributeMaxDynamicSharedMemorySize,
                         SMEM_CONV);
    cudaFuncSetAttribute(k_gemm_mma, cudaFuncAttributeMaxDynamicSharedMemorySize,
                         SMEM_GEMM);

    // fused prep: gen (1024 blocks) + prepW (2048) + xt (8192)
    k_prep<<<11264, 256>>>(log_dt, Arl, Aim, Cr, Ci, W, x, kern, wT, xt);

    k_conv_tc<<<HH, 256, SMEM_CONV>>>(xt, kern, D, yh);

    dim3 ggrid(1024 / 64, 16384 / 128);   // (16, 128)
    k_gemm_mma<<<ggrid, 256, SMEM_GEMM>>>(yh, wT, bias, out);
}